// round 8
// baseline (speedup 1.0000x reference)
#include <cuda_runtime.h>
#include <cuda_bf16.h>
#include <cstdint>
#include <math.h>

// Problem dims (fixed)
#define B_SZ   4096
#define N_IN   4096
#define N_CTX  512
#define UNITS  4096
#define RANK   256

// ---------------------------------------------------------------------------
// Device scratch (bf16 hi/lo split operands)
// ---------------------------------------------------------------------------
__device__ __align__(16) unsigned short g_in_hi[B_SZ * N_IN];   // inputs
__device__ __align__(16) unsigned short g_in_lo[B_SZ * N_IN];
__device__ __align__(16) unsigned short g_ctx_hi[B_SZ * N_CTX]; // context
__device__ __align__(16) unsigned short g_ctx_lo[B_SZ * N_CTX];
__device__ __align__(16) unsigned short g_t_hi[B_SZ * RANK];
__device__ __align__(16) unsigned short g_t_lo[B_SZ * RANK];
__device__ __align__(16) unsigned short g_Ut_hi[RANK * N_IN];   // U^T [256][4096]
__device__ __align__(16) unsigned short g_Ut_lo[RANK * N_IN];
__device__ __align__(16) unsigned short g_V_hi[UNITS * RANK];   // V [4096][256]
__device__ __align__(16) unsigned short g_V_lo[UNITS * RANK];
__device__ __align__(16) unsigned short g_Wt_hi[RANK * N_CTX];  // W^T [256][512]
__device__ __align__(16) unsigned short g_Wt_lo[RANK * N_CTX];
__device__ __align__(16) float          g_schi[B_SZ * RANK];

// ---------------------------------------------------------------------------
// Helpers
// ---------------------------------------------------------------------------
__device__ __forceinline__ uint32_t smem_to_u32(const void* p) {
    uint32_t a;
    asm("{ .reg .u64 t; cvta.to.shared.u64 t, %1; cvt.u32.u64 %0, t; }"
        : "=r"(a) : "l"(p));
    return a;
}

__device__ __forceinline__ void ldmx4(uint32_t* r, uint32_t addr) {
    asm volatile("ldmatrix.sync.aligned.m8n8.x4.shared.b16 {%0,%1,%2,%3}, [%4];\n"
                 : "=r"(r[0]), "=r"(r[1]), "=r"(r[2]), "=r"(r[3]) : "r"(addr));
}

__device__ __forceinline__ void mma_bf16(float* c, const uint32_t* a, const uint32_t* b) {
    asm volatile(
        "mma.sync.aligned.m16n8k16.row.col.f32.bf16.bf16.f32 "
        "{%0,%1,%2,%3}, {%4,%5,%6,%7}, {%8,%9}, {%0,%1,%2,%3};\n"
        : "+f"(c[0]), "+f"(c[1]), "+f"(c[2]), "+f"(c[3])
        : "r"(a[0]), "r"(a[1]), "r"(a[2]), "r"(a[3]), "r"(b[0]), "r"(b[1]));
}

#define CP_ASYNC16(saddr, gptr) \
    asm volatile("cp.async.cg.shared.global [%0], [%1], 16;\n" \
                 :: "r"(saddr), "l"(gptr))
#define CP_COMMIT() asm volatile("cp.async.commit_group;\n" ::: "memory")

template <int N>
__device__ __forceinline__ void cp_wait_group() {
    asm volatile("cp.async.wait_group %0;\n" :: "n"(N) : "memory");
}

__device__ __forceinline__ void split2(float x, unsigned short& h, unsigned short& l) {
    __nv_bfloat16 hb = __float2bfloat16_rn(x);
    h = *reinterpret_cast<unsigned short*>(&hb);
    float r = x - __bfloat162float(hb);
    __nv_bfloat16 lb = __float2bfloat16_rn(r);
    l = *reinterpret_cast<unsigned short*>(&lb);
}

// ---------------------------------------------------------------------------
// Conversion kernels — destinations selected in DEVICE code.
// ---------------------------------------------------------------------------
template <int DST>
__global__ __launch_bounds__(256)
void k_split(const float* __restrict__ src)
{
    unsigned short* dhi = (DST == 0) ? g_in_hi : (DST == 1) ? g_ctx_hi : g_V_hi;
    unsigned short* dlo = (DST == 0) ? g_in_lo : (DST == 1) ? g_ctx_lo : g_V_lo;
    size_t i = ((size_t)blockIdx.x * 256 + threadIdx.x) * 4;
    float4 v = *(const float4*)(src + i);
    ushort4 h, l;
    split2(v.x, h.x, l.x);
    split2(v.y, h.y, l.y);
    split2(v.z, h.z, l.z);
    split2(v.w, h.w, l.w);
    *(ushort4*)(dhi + i) = h;
    *(ushort4*)(dlo + i) = l;
}

// Transpose + split: src [R][C] fp32 -> dst [C][R] hi/lo bf16.
// DST=0 -> g_Ut (R=4096), DST=1 -> g_Wt (R=512)
template <int DST>
__global__ __launch_bounds__(256)
void k_conv_T(const float* __restrict__ src, int R, int C)
{
    __shared__ float tile[32][33];
    int c0 = blockIdx.x * 32;
    int r0 = blockIdx.y * 32;
    int tx = threadIdx.x, ty = threadIdx.y;
    for (int i = ty; i < 32; i += 8)
        tile[i][tx] = src[(size_t)(r0 + i) * C + c0 + tx];
    __syncthreads();
    unsigned short* dhi = (DST == 0) ? g_Ut_hi : g_Wt_hi;
    unsigned short* dlo = (DST == 0) ? g_Ut_lo : g_Wt_lo;
    for (int i = ty; i < 32; i += 8) {
        int c = c0 + i, r = r0 + tx;
        float x = tile[tx][i];
        unsigned short h, l;
        split2(x, h, l);
        dhi[(size_t)c * R + r] = h;
        dlo[(size_t)c * R + r] = l;
    }
}

// ---------------------------------------------------------------------------
// Unified split-bf16 mma.sync GEMM, STAGES-deep cp.async pipeline.
//   C[TILEM x TILEN] per CTA over K = KTOT (chunks of 32).
//   A (bf16 hi/lo, [M][KTOT]): EPI0 g_ctx, EPI1 g_in, EPI2 g_t
//   B (bf16 hi/lo, [N][KTOT]): EPI0 g_Wt,  EPI1 g_Ut, EPI2 g_V
//   EPI 0: g_schi = S * sigmoid(acc + Bvec)
//   EPI 1: t = acc * g_schi -> g_t hi/lo
//   EPI 2: out = relu(acc + 2*bias)
// ---------------------------------------------------------------------------
template <int TILEM, int TILEN, int WARPS_M, int WARPS_N, int KTOT, int EPI,
          int STAGES, int MINCTA>
__global__ __launch_bounds__(WARPS_M * WARPS_N * 32, MINCTA)
void mma_gemm(float* __restrict__ outp,
              const float* __restrict__ ev0,   // EPI0: S, EPI2: bias
              const float* __restrict__ ev1)   // EPI0: Bvec
{
    constexpr int THREADS = WARPS_M * WARPS_N * 32;
    constexpr int WM = TILEM / WARPS_M;
    constexpr int MI = WM / 16;
    constexpr int NI = 4;                    // WN = 32 fixed
    constexpr int AHB = TILEM * 40 * 2;      // bytes per A half-stage (pitch 40 halves)
    constexpr int BHB = TILEN * 40 * 2;
    constexpr int STG = 2 * AHB + 2 * BHB;
    constexpr int NC  = KTOT / 32;
    constexpr int A_IT = TILEM * 4 / THREADS;
    constexpr int B_IT = TILEN * 4 / THREADS;
    static_assert(WARPS_N * 32 == TILEN, "tile mismatch");
    static_assert(WM % 16 == 0, "warp tile M");

    extern __shared__ char smem[];
    const uint32_t sb = smem_to_u32(smem);

    const int tid = threadIdx.x;
    const int wid = tid >> 5, lid = tid & 31;
    const int wm = wid / WARPS_N, wn = wid % WARPS_N;
    const int warp_row = wm * WM;
    const int warp_col = wn * 32;
    const int brow = blockIdx.y * TILEM;
    const int bn0  = blockIdx.x * TILEN;

    const unsigned short* Ahg = (EPI == 0) ? g_ctx_hi : (EPI == 1) ? g_in_hi : g_t_hi;
    const unsigned short* Alg = (EPI == 0) ? g_ctx_lo : (EPI == 1) ? g_in_lo : g_t_lo;
    const unsigned short* Bhg = (EPI == 0) ? g_Wt_hi : (EPI == 1) ? g_Ut_hi : g_V_hi;
    const unsigned short* Blg = (EPI == 0) ? g_Wt_lo : (EPI == 1) ? g_Ut_lo : g_V_lo;

    float acc[MI][NI][4];
#pragma unroll
    for (int mi = 0; mi < MI; mi++)
#pragma unroll
        for (int ni = 0; ni < NI; ni++)
#pragma unroll
            for (int q = 0; q < 4; q++) acc[mi][ni][q] = 0.f;

    // ldmatrix per-lane byte offsets (pitch = 40 halves = 80 B)
    const uint32_t a_lane = (uint32_t)(((lid & 15) * 40 + (lid >> 4) * 8) * 2);
    const uint32_t b_lane = (uint32_t)((((lid & 7) + ((lid >> 4) << 3)) * 40 +
                                        ((lid >> 3) & 1) * 8) * 2);

    // stage loader: issues cp.asyncs for chunk k0 into stage slot s
    auto load_stage = [&](int s, int k0) {
        const uint32_t st = sb + (uint32_t)(s * STG);
#pragma unroll
        for (int it = 0; it < A_IT; it++) {
            int flat = it * THREADS + tid;
            int row = flat >> 2, seg = flat & 3;
            uint32_t off = (uint32_t)(row * 80 + seg * 16);
            size_t gi = (size_t)(brow + row) * KTOT + k0 + seg * 8;
            CP_ASYNC16(st + off, Ahg + gi);
            CP_ASYNC16(st + AHB + off, Alg + gi);
        }
#pragma unroll
        for (int it = 0; it < B_IT; it++) {
            int flat = it * THREADS + tid;
            int row = flat >> 2, seg = flat & 3;
            uint32_t off = (uint32_t)(row * 80 + seg * 16);
            size_t gi = (size_t)(bn0 + row) * KTOT + k0 + seg * 8;
            CP_ASYNC16(st + 2 * AHB + off, Bhg + gi);
            CP_ASYNC16(st + 2 * AHB + BHB + off, Blg + gi);
        }
    };

    // prologue: fill STAGES-1 stages
#pragma unroll
    for (int s = 0; s < STAGES - 1; s++) {
        load_stage(s, s * 32);
        CP_COMMIT();
    }

    // main loop: wait -> sync -> issue next -> compute current
    for (int ch = 0; ch < NC; ch++) {
        cp_wait_group<STAGES - 2>();
        __syncthreads();

        if (ch + STAGES - 1 < NC)
            load_stage((ch + STAGES - 1) % STAGES, (ch + STAGES - 1) * 32);
        CP_COMMIT();   // always commit (possibly empty) to keep group accounting uniform

        const uint32_t cb = sb + (uint32_t)((ch % STAGES) * STG);
        const uint32_t Ah = cb, Al = cb + AHB, Bh = cb + 2 * AHB, Bl = Bh + BHB;
#pragma unroll
        for (int ks = 0; ks < 2; ks++) {
            uint32_t afh[MI][4], afl[MI][4], bfh[2][4], bfl[2][4];
#pragma unroll
            for (int mi = 0; mi < MI; mi++) {
                uint32_t ao = a_lane + (uint32_t)((warp_row + mi * 16) * 80 + ks * 32);
                ldmx4(afh[mi], Ah + ao);
                ldmx4(afl[mi], Al + ao);
            }
#pragma unroll
            for (int j = 0; j < 2; j++) {
                uint32_t bo = b_lane + (uint32_t)((warp_col + j * 16) * 80 + ks * 32);
                ldmx4(bfh[j], Bh + bo);
                ldmx4(bfl[j], Bl + bo);
            }
#pragma unroll
            for (int mi = 0; mi < MI; mi++) {
#pragma unroll
                for (int ni = 0; ni < NI; ni++) {
                    const uint32_t* bh = &bfh[ni >> 1][(ni & 1) * 2];
                    const uint32_t* bl = &bfl[ni >> 1][(ni & 1) * 2];
                    mma_bf16(acc[mi][ni], afh[mi], bh);
                    mma_bf16(acc[mi][ni], afh[mi], bl);
                    mma_bf16(acc[mi][ni], afl[mi], bh);
                }
            }
        }
    }

    // ---------------- epilogue ----------------
    const int g = lid >> 2, t = lid & 3;
#pragma unroll
    for (int mi = 0; mi < MI; mi++) {
#pragma unroll
        for (int ni = 0; ni < NI; ni++) {
            int row0 = brow + warp_row + mi * 16 + g;
            int row1 = row0 + 8;
            int col  = bn0 + warp_col + ni * 8 + 2 * t;
            const float* a = acc[mi][ni];
            if (EPI == 0) {
                float bv0 = ev1[col], bv1 = ev1[col + 1];
                float s0 = ev0[col], s1 = ev0[col + 1];
                float x00 = a[0] + bv0, x01 = a[1] + bv1;
                float x10 = a[2] + bv0, x11 = a[3] + bv1;
                float2 r0 = make_float2(s0 / (1.f + expf(-x00)), s1 / (1.f + expf(-x01)));
                float2 r1 = make_float2(s0 / (1.f + expf(-x10)), s1 / (1.f + expf(-x11)));
                *(float2*)(g_schi + (size_t)row0 * RANK + col) = r0;
                *(float2*)(g_schi + (size_t)row1 * RANK + col) = r1;
            } else if (EPI == 1) {
                size_t i0 = (size_t)row0 * RANK + col;
                size_t i1 = (size_t)row1 * RANK + col;
                float t00 = a[0] * g_schi[i0], t01 = a[1] * g_schi[i0 + 1];
                float t10 = a[2] * g_schi[i1], t11 = a[3] * g_schi[i1 + 1];
                ushort2 h0, l0, h1, l1;
                split2(t00, h0.x, l0.x); split2(t01, h0.y, l0.y);
                split2(t10, h1.x, l1.x); split2(t11, h1.y, l1.y);
                *(ushort2*)(g_t_hi + i0) = h0; *(ushort2*)(g_t_lo + i0) = l0;
                *(ushort2*)(g_t_hi + i1) = h1; *(ushort2*)(g_t_lo + i1) = l1;
            } else {
                float b0 = 2.f * ev0[col], b1 = 2.f * ev0[col + 1];
                float2 r0 = make_float2(fmaxf(a[0] + b0, 0.f), fmaxf(a[1] + b1, 0.f));
                float2 r1 = make_float2(fmaxf(a[2] + b0, 0.f), fmaxf(a[3] + b1, 0.f));
                *(float2*)(outp + (size_t)row0 * UNITS + col) = r0;
                *(float2*)(outp + (size_t)row1 * UNITS + col) = r1;
            }
        }
    }
}

// ---------------------------------------------------------------------------
// Launch. Input order:
// 0: inputs [4096,4096]  1: context [4096,512]  2: U [4096,256]  3: S [256]
// 4: V [4096,256]        5: W [512,256]         6: B [256]       7: bias [4096]
// ---------------------------------------------------------------------------
extern "C" void kernel_launch(void* const* d_in, const int* in_sizes, int n_in,
                              void* d_out, int out_size)
{
    const float* inputs  = (const float*)d_in[0];
    const float* context = (const float*)d_in[1];
    const float* U       = (const float*)d_in[2];
    const float* S       = (const float*)d_in[3];
    const float* V       = (const float*)d_in[4];
    const float* W       = (const float*)d_in[5];
    const float* Bvec    = (const float*)d_in[6];
    const float* bias    = (const float*)d_in[7];
    float* out = (float*)d_out;

    // chi / gemm1: 64x64 tiles, 128 thr (2x2 warps), 4 stages -> 81920 B
    // gemm2:       128x64 tiles, 128 thr (2x2 warps), 2 stages -> 61440 B
    const int smem_64  = 4 * (64 + 64) * 160;    // 81920
    const int smem_g2  = 2 * (128 + 64) * 160;   // 61440

    cudaFuncSetAttribute(mma_gemm<64, 64, 2, 2, 512, 0, 4, 2>,
                         cudaFuncAttributeMaxDynamicSharedMemorySize, smem_64);
    cudaFuncSetAttribute(mma_gemm<64, 64, 2, 2, 4096, 1, 4, 2>,
                         cudaFuncAttributeMaxDynamicSharedMemorySize, smem_64);
    cudaFuncSetAttribute(mma_gemm<128, 64, 2, 2, 256, 2, 2, 3>,
                         cudaFuncAttributeMaxDynamicSharedMemorySize, smem_g2);

    // conversions (bf16 hi/lo splits)
    k_split<0><<<(size_t)B_SZ * N_IN / 1024, 256>>>(inputs);
    k_split<1><<<(size_t)B_SZ * N_CTX / 1024, 256>>>(context);
    k_split<2><<<(size_t)UNITS * RANK / 1024, 256>>>(V);
    k_conv_T<0><<<dim3(RANK / 32, N_IN / 32), dim3(32, 8)>>>(U, N_IN, RANK);
    k_conv_T<1><<<dim3(RANK / 32, N_CTX / 32), dim3(32, 8)>>>(W, N_CTX, RANK);

    // chi: schi = S*sigmoid(context @ W^T + B)   [4096 x 256], K=512
    mma_gemm<64, 64, 2, 2, 512, 0, 4, 2><<<dim3(RANK / 64, B_SZ / 64), 128, smem_64>>>(
        nullptr, S, Bvec);
    // t = (inputs @ U) * schi  [4096 x 256], K=4096
    mma_gemm<64, 64, 2, 2, 4096, 1, 4, 2><<<dim3(RANK / 64, B_SZ / 64), 128, smem_64>>>(
        nullptr, nullptr, nullptr);
    // out = relu(t @ V^T + 2*bias)  [4096 x 4096], K=256
    mma_gemm<128, 64, 2, 2, 256, 2, 2, 3><<<dim3(UNITS / 64, B_SZ / 128), 128, smem_g2>>>(
        out, bias, nullptr);
}

// round 9
// speedup vs baseline: 1.0475x; 1.0475x over previous
#include <cuda_runtime.h>
#include <cuda_bf16.h>
#include <cstdint>
#include <math.h>

// Problem dims (fixed)
#define B_SZ   4096
#define N_IN   4096
#define N_CTX  512
#define UNITS  4096
#define RANK   256

// ---------------------------------------------------------------------------
// Device scratch (bf16 hi/lo split operands)
// ---------------------------------------------------------------------------
__device__ __align__(16) unsigned short g_ctx_hi[B_SZ * N_CTX]; // context
__device__ __align__(16) unsigned short g_ctx_lo[B_SZ * N_CTX];
__device__ __align__(16) unsigned short g_t_hi[B_SZ * RANK];
__device__ __align__(16) unsigned short g_t_lo[B_SZ * RANK];
__device__ __align__(16) unsigned short g_Ut_hi[RANK * N_IN];   // U^T [256][4096]
__device__ __align__(16) unsigned short g_Ut_lo[RANK * N_IN];
__device__ __align__(16) unsigned short g_V_hi[UNITS * RANK];   // V [4096][256]
__device__ __align__(16) unsigned short g_V_lo[UNITS * RANK];
__device__ __align__(16) unsigned short g_Wt_hi[RANK * N_CTX];  // W^T [256][512]
__device__ __align__(16) unsigned short g_Wt_lo[RANK * N_CTX];
__device__ __align__(16) float          g_schi[B_SZ * RANK];

// ---------------------------------------------------------------------------
// Helpers
// ---------------------------------------------------------------------------
__device__ __forceinline__ uint32_t smem_to_u32(const void* p) {
    uint32_t a;
    asm("{ .reg .u64 t; cvta.to.shared.u64 t, %1; cvt.u32.u64 %0, t; }"
        : "=r"(a) : "l"(p));
    return a;
}

__device__ __forceinline__ void ldmx4(uint32_t* r, uint32_t addr) {
    asm volatile("ldmatrix.sync.aligned.m8n8.x4.shared.b16 {%0,%1,%2,%3}, [%4];\n"
                 : "=r"(r[0]), "=r"(r[1]), "=r"(r[2]), "=r"(r[3]) : "r"(addr));
}

__device__ __forceinline__ void mma_bf16(float* c, const uint32_t* a, const uint32_t* b) {
    asm volatile(
        "mma.sync.aligned.m16n8k16.row.col.f32.bf16.bf16.f32 "
        "{%0,%1,%2,%3}, {%4,%5,%6,%7}, {%8,%9}, {%0,%1,%2,%3};\n"
        : "+f"(c[0]), "+f"(c[1]), "+f"(c[2]), "+f"(c[3])
        : "r"(a[0]), "r"(a[1]), "r"(a[2]), "r"(a[3]), "r"(b[0]), "r"(b[1]));
}

#define CP_ASYNC16(saddr, gptr) \
    asm volatile("cp.async.cg.shared.global [%0], [%1], 16;\n" \
                 :: "r"(saddr), "l"(gptr))
#define CP_COMMIT() asm volatile("cp.async.commit_group;\n" ::: "memory")

template <int N>
__device__ __forceinline__ void cp_wait_group() {
    asm volatile("cp.async.wait_group %0;\n" :: "n"(N) : "memory");
}

__device__ __forceinline__ void split2(float x, unsigned short& h, unsigned short& l) {
    __nv_bfloat16 hb = __float2bfloat16_rn(x);
    h = *reinterpret_cast<unsigned short*>(&hb);
    float r = x - __bfloat162float(hb);
    __nv_bfloat16 lb = __float2bfloat16_rn(r);
    l = *reinterpret_cast<unsigned short*>(&lb);
}

// ---------------------------------------------------------------------------
// Conversion kernels — destinations selected in DEVICE code.
// ---------------------------------------------------------------------------
// DST: 1=context, 2=V
template <int DST>
__global__ __launch_bounds__(256)
void k_split(const float* __restrict__ src)
{
    unsigned short* dhi = (DST == 1) ? g_ctx_hi : g_V_hi;
    unsigned short* dlo = (DST == 1) ? g_ctx_lo : g_V_lo;
    size_t i = ((size_t)blockIdx.x * 256 + threadIdx.x) * 4;
    float4 v = *(const float4*)(src + i);
    ushort4 h, l;
    split2(v.x, h.x, l.x);
    split2(v.y, h.y, l.y);
    split2(v.z, h.z, l.z);
    split2(v.w, h.w, l.w);
    *(ushort4*)(dhi + i) = h;
    *(ushort4*)(dlo + i) = l;
}

// Transpose + split: src [R][C] fp32 -> dst [C][R] hi/lo bf16.
// DST=0 -> g_Ut (R=4096), DST=1 -> g_Wt (R=512)
template <int DST>
__global__ __launch_bounds__(256)
void k_conv_T(const float* __restrict__ src, int R, int C)
{
    __shared__ float tile[32][33];
    int c0 = blockIdx.x * 32;
    int r0 = blockIdx.y * 32;
    int tx = threadIdx.x, ty = threadIdx.y;
    for (int i = ty; i < 32; i += 8)
        tile[i][tx] = src[(size_t)(r0 + i) * C + c0 + tx];
    __syncthreads();
    unsigned short* dhi = (DST == 0) ? g_Ut_hi : g_Wt_hi;
    unsigned short* dlo = (DST == 0) ? g_Ut_lo : g_Wt_lo;
    for (int i = ty; i < 32; i += 8) {
        int c = c0 + i, r = r0 + tx;
        float x = tile[tx][i];
        unsigned short h, l;
        split2(x, h, l);
        dhi[(size_t)c * R + r] = h;
        dlo[(size_t)c * R + r] = l;
    }
}

// ---------------------------------------------------------------------------
// Template GEMM (pre-split A), R6 geometry. EPI 0 (chi) and 2 (out).
//   C[TILEM x TILEN], 256 threads, 4-stage cp.async for A and B.
// ---------------------------------------------------------------------------
template <int TILEM, int TILEN, int WARPS_M, int WARPS_N, int KTOT, int EPI,
          int STAGES>
__global__ __launch_bounds__(WARPS_M * WARPS_N * 32, 1)
void mma_gemm(float* __restrict__ outp,
              const float* __restrict__ ev0,   // EPI0: S, EPI2: bias
              const float* __restrict__ ev1)   // EPI0: Bvec
{
    constexpr int THREADS = WARPS_M * WARPS_N * 32;
    constexpr int WM = TILEM / WARPS_M;
    constexpr int MI = WM / 16;
    constexpr int NI = 4;                    // WN = 32 fixed
    constexpr int AHB = TILEM * 40 * 2;
    constexpr int BHB = TILEN * 40 * 2;
    constexpr int STG = 2 * AHB + 2 * BHB;
    constexpr int NC  = KTOT / 32;
    constexpr int A_IT = TILEM * 4 / THREADS;
    constexpr int B_IT = TILEN * 4 / THREADS;
    static_assert(WARPS_N * 32 == TILEN, "tile mismatch");

    extern __shared__ char smem[];
    const uint32_t sb = smem_to_u32(smem);

    const int tid = threadIdx.x;
    const int wid = tid >> 5, lid = tid & 31;
    const int wm = wid / WARPS_N, wn = wid % WARPS_N;
    const int warp_row = wm * WM;
    const int warp_col = wn * 32;
    const int brow = blockIdx.y * TILEM;
    const int bn0  = blockIdx.x * TILEN;

    const unsigned short* Ahg = (EPI == 0) ? g_ctx_hi : g_t_hi;
    const unsigned short* Alg = (EPI == 0) ? g_ctx_lo : g_t_lo;
    const unsigned short* Bhg = (EPI == 0) ? g_Wt_hi : g_V_hi;
    const unsigned short* Blg = (EPI == 0) ? g_Wt_lo : g_V_lo;

    float acc[MI][NI][4];
#pragma unroll
    for (int mi = 0; mi < MI; mi++)
#pragma unroll
        for (int ni = 0; ni < NI; ni++)
#pragma unroll
            for (int q = 0; q < 4; q++) acc[mi][ni][q] = 0.f;

    const uint32_t a_lane = (uint32_t)(((lid & 15) * 40 + (lid >> 4) * 8) * 2);
    const uint32_t b_lane = (uint32_t)((((lid & 7) + ((lid >> 4) << 3)) * 40 +
                                        ((lid >> 3) & 1) * 8) * 2);

    auto load_stage = [&](int s, int k0) {
        const uint32_t st = sb + (uint32_t)(s * STG);
#pragma unroll
        for (int it = 0; it < A_IT; it++) {
            int flat = it * THREADS + tid;
            int row = flat >> 2, seg = flat & 3;
            uint32_t off = (uint32_t)(row * 80 + seg * 16);
            size_t gi = (size_t)(brow + row) * KTOT + k0 + seg * 8;
            CP_ASYNC16(st + off, Ahg + gi);
            CP_ASYNC16(st + AHB + off, Alg + gi);
        }
#pragma unroll
        for (int it = 0; it < B_IT; it++) {
            int flat = it * THREADS + tid;
            int row = flat >> 2, seg = flat & 3;
            uint32_t off = (uint32_t)(row * 80 + seg * 16);
            size_t gi = (size_t)(bn0 + row) * KTOT + k0 + seg * 8;
            CP_ASYNC16(st + 2 * AHB + off, Bhg + gi);
            CP_ASYNC16(st + 2 * AHB + BHB + off, Blg + gi);
        }
    };

#pragma unroll
    for (int s = 0; s < STAGES - 1; s++) {
        load_stage(s, s * 32);
        CP_COMMIT();
    }

    for (int ch = 0; ch < NC; ch++) {
        cp_wait_group<STAGES - 2>();
        __syncthreads();

        if (ch + STAGES - 1 < NC)
            load_stage((ch + STAGES - 1) % STAGES, (ch + STAGES - 1) * 32);
        CP_COMMIT();

        const uint32_t cb = sb + (uint32_t)((ch % STAGES) * STG);
        const uint32_t Ah = cb, Al = cb + AHB, Bh = cb + 2 * AHB, Bl = Bh + BHB;
#pragma unroll
        for (int ks = 0; ks < 2; ks++) {
            uint32_t afh[MI][4], afl[MI][4], bfh[2][4], bfl[2][4];
#pragma unroll
            for (int mi = 0; mi < MI; mi++) {
                uint32_t ao = a_lane + (uint32_t)((warp_row + mi * 16) * 80 + ks * 32);
                ldmx4(afh[mi], Ah + ao);
                ldmx4(afl[mi], Al + ao);
            }
#pragma unroll
            for (int j = 0; j < 2; j++) {
                uint32_t bo = b_lane + (uint32_t)((warp_col + j * 16) * 80 + ks * 32);
                ldmx4(bfh[j], Bh + bo);
                ldmx4(bfl[j], Bl + bo);
            }
#pragma unroll
            for (int mi = 0; mi < MI; mi++) {
#pragma unroll
                for (int ni = 0; ni < NI; ni++) {
                    const uint32_t* bh = &bfh[ni >> 1][(ni & 1) * 2];
                    const uint32_t* bl = &bfl[ni >> 1][(ni & 1) * 2];
                    mma_bf16(acc[mi][ni], afh[mi], bh);
                    mma_bf16(acc[mi][ni], afh[mi], bl);
                    mma_bf16(acc[mi][ni], afl[mi], bh);
                }
            }
        }
    }

    const int g = lid >> 2, t = lid & 3;
#pragma unroll
    for (int mi = 0; mi < MI; mi++) {
#pragma unroll
        for (int ni = 0; ni < NI; ni++) {
            int row0 = brow + warp_row + mi * 16 + g;
            int row1 = row0 + 8;
            int col  = bn0 + warp_col + ni * 8 + 2 * t;
            const float* a = acc[mi][ni];
            if (EPI == 0) {
                float bv0 = ev1[col], bv1 = ev1[col + 1];
                float s0 = ev0[col], s1 = ev0[col + 1];
                float x00 = a[0] + bv0, x01 = a[1] + bv1;
                float x10 = a[2] + bv0, x11 = a[3] + bv1;
                float2 r0 = make_float2(s0 / (1.f + expf(-x00)), s1 / (1.f + expf(-x01)));
                float2 r1 = make_float2(s0 / (1.f + expf(-x10)), s1 / (1.f + expf(-x11)));
                *(float2*)(g_schi + (size_t)row0 * RANK + col) = r0;
                *(float2*)(g_schi + (size_t)row1 * RANK + col) = r1;
            } else {
                float b0 = 2.f * ev0[col], b1 = 2.f * ev0[col + 1];
                float2 r0 = make_float2(fmaxf(a[0] + b0, 0.f), fmaxf(a[1] + b1, 0.f));
                float2 r1 = make_float2(fmaxf(a[2] + b0, 0.f), fmaxf(a[3] + b1, 0.f));
                *(float2*)(outp + (size_t)row0 * UNITS + col) = r0;
                *(float2*)(outp + (size_t)row1 * UNITS + col) = r1;
            }
        }
    }
}

// ---------------------------------------------------------------------------
// GEMM1 fused: t = (inputs @ U^T) * schi, A = fp32 inputs split on the fly.
//   128x64 tile, 256 threads (4x2 warps), K=4096.
//   A: LDG fp32 one chunk ahead -> convert -> STS (2 smem buffers)
//   B: 4-stage cp.async of pre-split U^T hi/lo
// ---------------------------------------------------------------------------
__global__ __launch_bounds__(256, 1)
void gemm1_fused(const float* __restrict__ Afp)
{
    constexpr int KTOT = N_IN;
    constexpr int NC = KTOT / 32;        // 128
    constexpr int AHB = 128 * 40 * 2;    // 10240 (one half: hi or lo)
    constexpr int ABUF = 2 * AHB;        // hi+lo per A stage
    constexpr int BHB = 64 * 40 * 2;     // 5120
    constexpr int BSTG = 2 * BHB;        // 10240
    // smem: A stages [0,2*ABUF) ; B stages [2*ABUF, 2*ABUF + 4*BSTG)

    extern __shared__ char smem[];
    const uint32_t sb = smem_to_u32(smem);
    const uint32_t sbB = sb + 2 * ABUF;

    const int tid = threadIdx.x;
    const int wid = tid >> 5, lid = tid & 31;
    const int wm = wid >> 1, wn = wid & 1;  // 4x2
    const int warp_row = wm * 32;           // WM=32, MI=2
    const int warp_col = wn * 32;
    const int brow = blockIdx.y * 128;
    const int bn0  = blockIdx.x * 64;

    float acc[2][4][4];
#pragma unroll
    for (int mi = 0; mi < 2; mi++)
#pragma unroll
        for (int ni = 0; ni < 4; ni++)
#pragma unroll
            for (int q = 0; q < 4; q++) acc[mi][ni][q] = 0.f;

    const uint32_t a_lane = (uint32_t)(((lid & 15) * 40 + (lid >> 4) * 8) * 2);
    const uint32_t b_lane = (uint32_t)((((lid & 7) + ((lid >> 4) << 3)) * 40 +
                                        ((lid >> 3) & 1) * 8) * 2);

    // A: 128 rows x 8 segs(4 floats) = 1024 tasks / 256 thr = 4 its
    const int a_row = tid >> 1;             // rows covered by pairs: flat>>3 below
    (void)a_row;
    auto ldgA = [&](int k0, float4* pf) {
#pragma unroll
        for (int it = 0; it < 4; it++) {
            int flat = it * 256 + tid;
            int row = flat >> 3, seg = flat & 7;
            pf[it] = *(const float4*)(Afp + (size_t)(brow + row) * KTOT + k0 + seg * 4);
        }
    };
    auto cvtA = [&](int s, const float4* pf) {
        uint32_t base = (uint32_t)(s * ABUF);
#pragma unroll
        for (int it = 0; it < 4; it++) {
            int flat = it * 256 + tid;
            int row = flat >> 3, seg = flat & 7;
            ushort4 h, l;
            split2(pf[it].x, h.x, l.x);
            split2(pf[it].y, h.y, l.y);
            split2(pf[it].z, h.z, l.z);
            split2(pf[it].w, h.w, l.w);
            uint32_t off = base + (uint32_t)(row * 80 + seg * 8);
            *(ushort4*)(smem + off) = h;
            *(ushort4*)(smem + off + AHB) = l;
        }
    };
    auto loadB = [&](int s, int k0) {
        uint32_t st = sbB + (uint32_t)(s * BSTG);
        int row = tid >> 2, seg = tid & 3;   // 64 rows x 4 segs = 256
        uint32_t off = (uint32_t)(row * 80 + seg * 16);
        size_t gi = (size_t)(bn0 + row) * KTOT + k0 + seg * 8;
        CP_ASYNC16(st + off, g_Ut_hi + gi);
        CP_ASYNC16(st + BHB + off, g_Ut_lo + gi);
    };

    // prologue
    float4 pf_cur[4], pf_nxt[4];
    ldgA(0, pf_cur);
    cvtA(0, pf_cur);            // A stage 0 = chunk 0
    ldgA(32, pf_cur);           // chunk 1 pending in regs
    loadB(0, 0);   CP_COMMIT();
    loadB(1, 32);  CP_COMMIT();
    loadB(2, 64);  CP_COMMIT();

    for (int ch = 0; ch < NC; ch++) {
        cp_wait_group<2>();
        __syncthreads();        // A stage ch&1 and B stage ch&3 now valid

        if (ch + 2 < NC) ldgA((ch + 2) * 32, pf_nxt);
        if (ch + 1 < NC) cvtA((ch + 1) & 1, pf_cur);
        if (ch + 3 < NC) loadB((ch + 3) & 3, (ch + 3) * 32);
        CP_COMMIT();

        const uint32_t Ah = sb + (uint32_t)((ch & 1) * ABUF);
        const uint32_t Al = Ah + AHB;
        const uint32_t Bh = sbB + (uint32_t)((ch & 3) * BSTG);
        const uint32_t Bl = Bh + BHB;
#pragma unroll
        for (int ks = 0; ks < 2; ks++) {
            uint32_t afh[2][4], afl[2][4], bfh[2][4], bfl[2][4];
#pragma unroll
            for (int mi = 0; mi < 2; mi++) {
                uint32_t ao = a_lane + (uint32_t)((warp_row + mi * 16) * 80 + ks * 32);
                ldmx4(afh[mi], Ah + ao);
                ldmx4(afl[mi], Al + ao);
            }
#pragma unroll
            for (int j = 0; j < 2; j++) {
                uint32_t bo = b_lane + (uint32_t)((warp_col + j * 16) * 80 + ks * 32);
                ldmx4(bfh[j], Bh + bo);
                ldmx4(bfl[j], Bl + bo);
            }
#pragma unroll
            for (int mi = 0; mi < 2; mi++) {
#pragma unroll
                for (int ni = 0; ni < 4; ni++) {
                    const uint32_t* bh = &bfh[ni >> 1][(ni & 1) * 2];
                    const uint32_t* bl = &bfl[ni >> 1][(ni & 1) * 2];
                    mma_bf16(acc[mi][ni], afh[mi], bh);
                    mma_bf16(acc[mi][ni], afh[mi], bl);
                    mma_bf16(acc[mi][ni], afl[mi], bh);
                }
            }
        }
#pragma unroll
        for (int q = 0; q < 4; q++) pf_cur[q] = pf_nxt[q];
    }

    // epilogue: t = acc * schi -> g_t hi/lo
    const int g = lid >> 2, t = lid & 3;
#pragma unroll
    for (int mi = 0; mi < 2; mi++) {
#pragma unroll
        for (int ni = 0; ni < 4; ni++) {
            int row0 = brow + warp_row + mi * 16 + g;
            int row1 = row0 + 8;
            int col  = bn0 + warp_col + ni * 8 + 2 * t;
            const float* a = acc[mi][ni];
            size_t i0 = (size_t)row0 * RANK + col;
            size_t i1 = (size_t)row1 * RANK + col;
            float t00 = a[0] * g_schi[i0], t01 = a[1] * g_schi[i0 + 1];
            float t10 = a[2] * g_schi[i1], t11 = a[3] * g_schi[i1 + 1];
            ushort2 h0, l0, h1, l1;
            split2(t00, h0.x, l0.x); split2(t01, h0.y, l0.y);
            split2(t10, h1.x, l1.x); split2(t11, h1.y, l1.y);
            *(ushort2*)(g_t_hi + i0) = h0; *(ushort2*)(g_t_lo + i0) = l0;
            *(ushort2*)(g_t_hi + i1) = h1; *(ushort2*)(g_t_lo + i1) = l1;
        }
    }
}

// ---------------------------------------------------------------------------
// Launch. Input order:
// 0: inputs [4096,4096]  1: context [4096,512]  2: U [4096,256]  3: S [256]
// 4: V [4096,256]        5: W [512,256]         6: B [256]       7: bias [4096]
// ---------------------------------------------------------------------------
extern "C" void kernel_launch(void* const* d_in, const int* in_sizes, int n_in,
                              void* d_out, int out_size)
{
    const float* inputs  = (const float*)d_in[0];
    const float* context = (const float*)d_in[1];
    const float* U       = (const float*)d_in[2];
    const float* S       = (const float*)d_in[3];
    const float* V       = (const float*)d_in[4];
    const float* W       = (const float*)d_in[5];
    const float* Bvec    = (const float*)d_in[6];
    const float* bias    = (const float*)d_in[7];
    float* out = (float*)d_out;

    // chi: 128x64, 4 stages -> 4*(128+64)*160 = 122880
    // gemm2: 128x128, 4 stages -> 4*(128+128)*160 = 163840
    // gemm1_fused: A 2*20480 + B 4*10240 = 81920
    const int smem_chi = 4 * (128 + 64) * 160;
    const int smem_g2  = 4 * (128 + 128) * 160;
    const int smem_g1  = 2 * (2 * 10240) + 4 * 10240;

    cudaFuncSetAttribute(mma_gemm<128, 64, 4, 2, 512, 0, 4>,
                         cudaFuncAttributeMaxDynamicSharedMemorySize, smem_chi);
    cudaFuncSetAttribute(gemm1_fused,
                         cudaFuncAttributeMaxDynamicSharedMemorySize, smem_g1);
    cudaFuncSetAttribute(mma_gemm<128, 128, 2, 4, 256, 2, 4>,
                         cudaFuncAttributeMaxDynamicSharedMemorySize, smem_g2);

    // conversions (context, V, U^T, W^T) — inputs handled in-kernel by gemm1
    k_split<1><<<(size_t)B_SZ * N_CTX / 1024, 256>>>(context);
    k_split<2><<<(size_t)UNITS * RANK / 1024, 256>>>(V);
    k_conv_T<0><<<dim3(RANK / 32, N_IN / 32), dim3(32, 8)>>>(U, N_IN, RANK);
    k_conv_T<1><<<dim3(RANK / 32, N_CTX / 32), dim3(32, 8)>>>(W, N_CTX, RANK);

    // chi: schi = S*sigmoid(context @ W^T + B)   [4096 x 256], K=512
    mma_gemm<128, 64, 4, 2, 512, 0, 4><<<dim3(RANK / 64, B_SZ / 128), 256, smem_chi>>>(
        nullptr, S, Bvec);
    // t = (inputs @ U^T) * schi  [4096 x 256], K=4096 (fused A split)
    gemm1_fused<<<dim3(RANK / 64, B_SZ / 128), 256, smem_g1>>>(inputs);
    // out = relu(t @ V^T + 2*bias)  [4096 x 4096], K=256
    mma_gemm<128, 128, 2, 4, 256, 2, 4><<<dim3(UNITS / 128, B_SZ / 128), 256, smem_g2>>>(
        out, bias, nullptr);
}

// round 10
// speedup vs baseline: 1.0570x; 1.0091x over previous
#include <cuda_runtime.h>
#include <cuda_bf16.h>
#include <cstdint>
#include <math.h>

// Problem dims (fixed)
#define B_SZ   4096
#define N_IN   4096
#define N_CTX  512
#define UNITS  4096
#define RANK   256

// ---------------------------------------------------------------------------
// Device scratch (bf16 hi/lo split operands)
// ---------------------------------------------------------------------------
__device__ __align__(16) unsigned short g_ctx_hi[B_SZ * N_CTX]; // context
__device__ __align__(16) unsigned short g_ctx_lo[B_SZ * N_CTX];
__device__ __align__(16) unsigned short g_t_hi[B_SZ * RANK];
__device__ __align__(16) unsigned short g_t_lo[B_SZ * RANK];
__device__ __align__(16) unsigned short g_Ut_hi[RANK * N_IN];   // U^T [256][4096]
__device__ __align__(16) unsigned short g_Ut_lo[RANK * N_IN];
__device__ __align__(16) unsigned short g_V_hi[UNITS * RANK];   // V [4096][256]
__device__ __align__(16) unsigned short g_V_lo[UNITS * RANK];
__device__ __align__(16) unsigned short g_Wt_hi[RANK * N_CTX];  // W^T [256][512]
__device__ __align__(16) unsigned short g_Wt_lo[RANK * N_CTX];
__device__ __align__(16) float          g_schi[B_SZ * RANK];

// ---------------------------------------------------------------------------
// Helpers
// ---------------------------------------------------------------------------
__device__ __forceinline__ uint32_t smem_to_u32(const void* p) {
    uint32_t a;
    asm("{ .reg .u64 t; cvta.to.shared.u64 t, %1; cvt.u32.u64 %0, t; }"
        : "=r"(a) : "l"(p));
    return a;
}

__device__ __forceinline__ void ldmx4(uint32_t* r, uint32_t addr) {
    asm volatile("ldmatrix.sync.aligned.m8n8.x4.shared.b16 {%0,%1,%2,%3}, [%4];\n"
                 : "=r"(r[0]), "=r"(r[1]), "=r"(r[2]), "=r"(r[3]) : "r"(addr));
}

__device__ __forceinline__ void mma_bf16(float* c, const uint32_t* a, const uint32_t* b) {
    asm volatile(
        "mma.sync.aligned.m16n8k16.row.col.f32.bf16.bf16.f32 "
        "{%0,%1,%2,%3}, {%4,%5,%6,%7}, {%8,%9}, {%0,%1,%2,%3};\n"
        : "+f"(c[0]), "+f"(c[1]), "+f"(c[2]), "+f"(c[3])
        : "r"(a[0]), "r"(a[1]), "r"(a[2]), "r"(a[3]), "r"(b[0]), "r"(b[1]));
}

#define CP_ASYNC16(saddr, gptr) \
    asm volatile("cp.async.cg.shared.global [%0], [%1], 16;\n" \
                 :: "r"(saddr), "l"(gptr))
#define CP_COMMIT() asm volatile("cp.async.commit_group;\n" ::: "memory")

template <int N>
__device__ __forceinline__ void cp_wait_group() {
    asm volatile("cp.async.wait_group %0;\n" :: "n"(N) : "memory");
}

__device__ __forceinline__ void split2(float x, unsigned short& h, unsigned short& l) {
    __nv_bfloat16 hb = __float2bfloat16_rn(x);
    h = *reinterpret_cast<unsigned short*>(&hb);
    float r = x - __bfloat162float(hb);
    __nv_bfloat16 lb = __float2bfloat16_rn(r);
    l = *reinterpret_cast<unsigned short*>(&lb);
}

// ---------------------------------------------------------------------------
// Fused prep kernels (fewer launches; also positions gemm1 at profile slot 3)
// ---------------------------------------------------------------------------
// prep1: blocks [0,2048): split context -> g_ctx_hi/lo
//        blocks [2048,2176): transpose+split W[512][256] -> g_Wt[256][512]
__global__ __launch_bounds__(256)
void prep1(const float* __restrict__ ctx, const float* __restrict__ W)
{
    __shared__ float tile[32][33];
    int b = blockIdx.x, tid = threadIdx.x;
    if (b < 2048) {
        size_t i = ((size_t)b * 256 + tid) * 4;
        float4 v = *(const float4*)(ctx + i);
        ushort4 h, l;
        split2(v.x, h.x, l.x); split2(v.y, h.y, l.y);
        split2(v.z, h.z, l.z); split2(v.w, h.w, l.w);
        *(ushort4*)(g_ctx_hi + i) = h;
        *(ushort4*)(g_ctx_lo + i) = l;
    } else {
        int bb = b - 2048;                 // W: R=512 rows, C=256 cols
        int c0 = (bb & 7) * 32;            // C/32 = 8
        int r0 = (bb >> 3) * 32;           // R/32 = 16
        int tx = tid & 31, ty = tid >> 5;  // (32,8)
        for (int i = ty; i < 32; i += 8)
            tile[i][tx] = W[(size_t)(r0 + i) * RANK + c0 + tx];
        __syncthreads();
        for (int i = ty; i < 32; i += 8) {
            int c = c0 + i, r = r0 + tx;
            unsigned short h, l;
            split2(tile[tx][i], h, l);
            g_Wt_hi[(size_t)c * N_CTX + r] = h;
            g_Wt_lo[(size_t)c * N_CTX + r] = l;
        }
    }
}

// prep2: blocks [0,1024): split V -> g_V_hi/lo
//        blocks [1024,2048): transpose+split U[4096][256] -> g_Ut[256][4096]
__global__ __launch_bounds__(256)
void prep2(const float* __restrict__ V, const float* __restrict__ U)
{
    __shared__ float tile[32][33];
    int b = blockIdx.x, tid = threadIdx.x;
    if (b < 1024) {
        size_t i = ((size_t)b * 256 + tid) * 4;
        float4 v = *(const float4*)(V + i);
        ushort4 h, l;
        split2(v.x, h.x, l.x); split2(v.y, h.y, l.y);
        split2(v.z, h.z, l.z); split2(v.w, h.w, l.w);
        *(ushort4*)(g_V_hi + i) = h;
        *(ushort4*)(g_V_lo + i) = l;
    } else {
        int bb = b - 1024;                 // U: R=4096 rows, C=256 cols
        int c0 = (bb & 7) * 32;            // C/32 = 8
        int r0 = (bb >> 3) * 32;           // R/32 = 128
        int tx = tid & 31, ty = tid >> 5;
        for (int i = ty; i < 32; i += 8)
            tile[i][tx] = U[(size_t)(r0 + i) * RANK + c0 + tx];
        __syncthreads();
        for (int i = ty; i < 32; i += 8) {
            int c = c0 + i, r = r0 + tx;
            unsigned short h, l;
            split2(tile[tx][i], h, l);
            g_Ut_hi[(size_t)c * N_IN + r] = h;
            g_Ut_lo[(size_t)c * N_IN + r] = l;
        }
    }
}

// ---------------------------------------------------------------------------
// Template GEMM (pre-split A). EPI 0 (chi) and 2 (out).
// ---------------------------------------------------------------------------
template <int TILEM, int TILEN, int WARPS_M, int WARPS_N, int KTOT, int EPI,
          int STAGES>
__global__ __launch_bounds__(WARPS_M * WARPS_N * 32, 1)
void mma_gemm(float* __restrict__ outp,
              const float* __restrict__ ev0,   // EPI0: S, EPI2: bias
              const float* __restrict__ ev1)   // EPI0: Bvec
{
    constexpr int THREADS = WARPS_M * WARPS_N * 32;
    constexpr int WM = TILEM / WARPS_M;
    constexpr int MI = WM / 16;
    constexpr int NI = 4;
    constexpr int AHB = TILEM * 40 * 2;
    constexpr int BHB = TILEN * 40 * 2;
    constexpr int STG = 2 * AHB + 2 * BHB;
    constexpr int NC  = KTOT / 32;
    constexpr int A_IT = TILEM * 4 / THREADS;
    constexpr int B_IT = TILEN * 4 / THREADS;
    static_assert(WARPS_N * 32 == TILEN, "tile mismatch");

    extern __shared__ char smem[];
    const uint32_t sb = smem_to_u32(smem);

    const int tid = threadIdx.x;
    const int wid = tid >> 5, lid = tid & 31;
    const int wm = wid / WARPS_N, wn = wid % WARPS_N;
    const int warp_row = wm * WM;
    const int warp_col = wn * 32;
    const int brow = blockIdx.y * TILEM;
    const int bn0  = blockIdx.x * TILEN;

    const unsigned short* Ahg = (EPI == 0) ? g_ctx_hi : g_t_hi;
    const unsigned short* Alg = (EPI == 0) ? g_ctx_lo : g_t_lo;
    const unsigned short* Bhg = (EPI == 0) ? g_Wt_hi : g_V_hi;
    const unsigned short* Blg = (EPI == 0) ? g_Wt_lo : g_V_lo;

    float acc[MI][NI][4];
#pragma unroll
    for (int mi = 0; mi < MI; mi++)
#pragma unroll
        for (int ni = 0; ni < NI; ni++)
#pragma unroll
            for (int q = 0; q < 4; q++) acc[mi][ni][q] = 0.f;

    const uint32_t a_lane = (uint32_t)(((lid & 15) * 40 + (lid >> 4) * 8) * 2);
    const uint32_t b_lane = (uint32_t)((((lid & 7) + ((lid >> 4) << 3)) * 40 +
                                        ((lid >> 3) & 1) * 8) * 2);

    auto load_stage = [&](int s, int k0) {
        const uint32_t st = sb + (uint32_t)(s * STG);
#pragma unroll
        for (int it = 0; it < A_IT; it++) {
            int flat = it * THREADS + tid;
            int row = flat >> 2, seg = flat & 3;
            uint32_t off = (uint32_t)(row * 80 + seg * 16);
            size_t gi = (size_t)(brow + row) * KTOT + k0 + seg * 8;
            CP_ASYNC16(st + off, Ahg + gi);
            CP_ASYNC16(st + AHB + off, Alg + gi);
        }
#pragma unroll
        for (int it = 0; it < B_IT; it++) {
            int flat = it * THREADS + tid;
            int row = flat >> 2, seg = flat & 3;
            uint32_t off = (uint32_t)(row * 80 + seg * 16);
            size_t gi = (size_t)(bn0 + row) * KTOT + k0 + seg * 8;
            CP_ASYNC16(st + 2 * AHB + off, Bhg + gi);
            CP_ASYNC16(st + 2 * AHB + BHB + off, Blg + gi);
        }
    };

#pragma unroll
    for (int s = 0; s < STAGES - 1; s++) {
        load_stage(s, s * 32);
        CP_COMMIT();
    }

    for (int ch = 0; ch < NC; ch++) {
        cp_wait_group<STAGES - 2>();
        __syncthreads();

        if (ch + STAGES - 1 < NC)
            load_stage((ch + STAGES - 1) % STAGES, (ch + STAGES - 1) * 32);
        CP_COMMIT();

        const uint32_t cb = sb + (uint32_t)((ch % STAGES) * STG);
        const uint32_t Ah = cb, Al = cb + AHB, Bh = cb + 2 * AHB, Bl = Bh + BHB;
#pragma unroll
        for (int ks = 0; ks < 2; ks++) {
            uint32_t afh[MI][4], afl[MI][4], bfh[2][4], bfl[2][4];
#pragma unroll
            for (int mi = 0; mi < MI; mi++) {
                uint32_t ao = a_lane + (uint32_t)((warp_row + mi * 16) * 80 + ks * 32);
                ldmx4(afh[mi], Ah + ao);
                ldmx4(afl[mi], Al + ao);
            }
#pragma unroll
            for (int j = 0; j < 2; j++) {
                uint32_t bo = b_lane + (uint32_t)((warp_col + j * 16) * 80 + ks * 32);
                ldmx4(bfh[j], Bh + bo);
                ldmx4(bfl[j], Bl + bo);
            }
#pragma unroll
            for (int mi = 0; mi < MI; mi++) {
#pragma unroll
                for (int ni = 0; ni < NI; ni++) {
                    const uint32_t* bh = &bfh[ni >> 1][(ni & 1) * 2];
                    const uint32_t* bl = &bfl[ni >> 1][(ni & 1) * 2];
                    mma_bf16(acc[mi][ni], afh[mi], bh);
                    mma_bf16(acc[mi][ni], afh[mi], bl);
                    mma_bf16(acc[mi][ni], afl[mi], bh);
                }
            }
        }
    }

    const int g = lid >> 2, t = lid & 3;
#pragma unroll
    for (int mi = 0; mi < MI; mi++) {
#pragma unroll
        for (int ni = 0; ni < NI; ni++) {
            int row0 = brow + warp_row + mi * 16 + g;
            int row1 = row0 + 8;
            int col  = bn0 + warp_col + ni * 8 + 2 * t;
            const float* a = acc[mi][ni];
            if (EPI == 0) {
                float bv0 = ev1[col], bv1 = ev1[col + 1];
                float s0 = ev0[col], s1 = ev0[col + 1];
                float x00 = a[0] + bv0, x01 = a[1] + bv1;
                float x10 = a[2] + bv0, x11 = a[3] + bv1;
                float2 r0 = make_float2(s0 / (1.f + expf(-x00)), s1 / (1.f + expf(-x01)));
                float2 r1 = make_float2(s0 / (1.f + expf(-x10)), s1 / (1.f + expf(-x11)));
                *(float2*)(g_schi + (size_t)row0 * RANK + col) = r0;
                *(float2*)(g_schi + (size_t)row1 * RANK + col) = r1;
            } else {
                float b0 = 2.f * ev0[col], b1 = 2.f * ev0[col + 1];
                float2 r0 = make_float2(fmaxf(a[0] + b0, 0.f), fmaxf(a[1] + b1, 0.f));
                float2 r1 = make_float2(fmaxf(a[2] + b0, 0.f), fmaxf(a[3] + b1, 0.f));
                *(float2*)(outp + (size_t)row0 * UNITS + col) = r0;
                *(float2*)(outp + (size_t)row1 * UNITS + col) = r1;
            }
        }
    }
}

// ---------------------------------------------------------------------------
// GEMM1 fused: t = (inputs @ U^T) * schi; fp32 A split on the fly.
//   128x64 tile, 256 threads (4x2 warps), K=4096.
//   A: LDG fp32 one chunk ahead -> convert -> STS (2 smem stages)
//   B: 6-stage cp.async of pre-split U^T hi/lo
// ---------------------------------------------------------------------------
__global__ __launch_bounds__(256, 1)
void gemm1_fused(const float* __restrict__ Afp)
{
    constexpr int KTOT = N_IN;
    constexpr int NC = KTOT / 32;        // 128
    constexpr int AHB = 128 * 40 * 2;    // 10240
    constexpr int ABUF = 2 * AHB;        // 20480 (hi+lo per A stage)
    constexpr int BHB = 64 * 40 * 2;     // 5120
    constexpr int BSTG = 2 * BHB;        // 10240
    constexpr int BSTAGES = 6;

    extern __shared__ char smem[];
    const uint32_t sb = smem_to_u32(smem);
    const uint32_t sbB = sb + 2 * ABUF;

    const int tid = threadIdx.x;
    const int wid = tid >> 5, lid = tid & 31;
    const int wm = wid >> 1, wn = wid & 1;  // 4x2 warps
    const int warp_row = wm * 32;           // WM=32, MI=2
    const int warp_col = wn * 32;
    const int brow = blockIdx.y * 128;
    const int bn0  = blockIdx.x * 64;

    float acc[2][4][4];
#pragma unroll
    for (int mi = 0; mi < 2; mi++)
#pragma unroll
        for (int ni = 0; ni < 4; ni++)
#pragma unroll
            for (int q = 0; q < 4; q++) acc[mi][ni][q] = 0.f;

    const uint32_t a_lane = (uint32_t)(((lid & 15) * 40 + (lid >> 4) * 8) * 2);
    const uint32_t b_lane = (uint32_t)((((lid & 7) + ((lid >> 4) << 3)) * 40 +
                                        ((lid >> 3) & 1) * 8) * 2);

    auto ldgA = [&](int k0, float4* pf) {
#pragma unroll
        for (int it = 0; it < 4; it++) {
            int flat = it * 256 + tid;
            int row = flat >> 3, seg = flat & 7;
            pf[it] = *(const float4*)(Afp + (size_t)(brow + row) * KTOT + k0 + seg * 4);
        }
    };
    auto cvtA = [&](int s, const float4* pf) {
        uint32_t base = (uint32_t)(s * ABUF);
#pragma unroll
        for (int it = 0; it < 4; it++) {
            int flat = it * 256 + tid;
            int row = flat >> 3, seg = flat & 7;
            ushort4 h, l;
            split2(pf[it].x, h.x, l.x);
            split2(pf[it].y, h.y, l.y);
            split2(pf[it].z, h.z, l.z);
            split2(pf[it].w, h.w, l.w);
            uint32_t off = base + (uint32_t)(row * 80 + seg * 8);
            *(ushort4*)(smem + off) = h;
            *(ushort4*)(smem + off + AHB) = l;
        }
    };
    auto loadB = [&](int s, int k0) {
        uint32_t st = sbB + (uint32_t)(s * BSTG);
        int row = tid >> 2, seg = tid & 3;
        uint32_t off = (uint32_t)(row * 80 + seg * 16);
        size_t gi = (size_t)(bn0 + row) * KTOT + k0 + seg * 8;
        CP_ASYNC16(st + off, g_Ut_hi + gi);
        CP_ASYNC16(st + BHB + off, g_Ut_lo + gi);
    };

    // prologue
    float4 pf_cur[4], pf_nxt[4];
    ldgA(0, pf_cur);
    cvtA(0, pf_cur);            // A stage 0 = chunk 0
    ldgA(32, pf_cur);           // chunk 1 pending in regs
#pragma unroll
    for (int s = 0; s < BSTAGES - 1; s++) {
        loadB(s, s * 32);
        CP_COMMIT();
    }

    for (int ch = 0; ch < NC; ch++) {
        cp_wait_group<BSTAGES - 2>();
        __syncthreads();        // A stage ch&1 and B stage ch%BSTAGES valid

        if (ch + 2 < NC) ldgA((ch + 2) * 32, pf_nxt);
        if (ch + 1 < NC) cvtA((ch + 1) & 1, pf_cur);
        if (ch + BSTAGES - 1 < NC)
            loadB((ch + BSTAGES - 1) % BSTAGES, (ch + BSTAGES - 1) * 32);
        CP_COMMIT();

        const uint32_t Ah = sb + (uint32_t)((ch & 1) * ABUF);
        const uint32_t Al = Ah + AHB;
        const uint32_t Bh = sbB + (uint32_t)((ch % BSTAGES) * BSTG);
        const uint32_t Bl = Bh + BHB;
#pragma unroll
        for (int ks = 0; ks < 2; ks++) {
            uint32_t afh[2][4], afl[2][4], bfh[2][4], bfl[2][4];
#pragma unroll
            for (int mi = 0; mi < 2; mi++) {
                uint32_t ao = a_lane + (uint32_t)((warp_row + mi * 16) * 80 + ks * 32);
                ldmx4(afh[mi], Ah + ao);
                ldmx4(afl[mi], Al + ao);
            }
#pragma unroll
            for (int j = 0; j < 2; j++) {
                uint32_t bo = b_lane + (uint32_t)((warp_col + j * 16) * 80 + ks * 32);
                ldmx4(bfh[j], Bh + bo);
                ldmx4(bfl[j], Bl + bo);
            }
#pragma unroll
            for (int mi = 0; mi < 2; mi++) {
#pragma unroll
                for (int ni = 0; ni < 4; ni++) {
                    const uint32_t* bh = &bfh[ni >> 1][(ni & 1) * 2];
                    const uint32_t* bl = &bfl[ni >> 1][(ni & 1) * 2];
                    mma_bf16(acc[mi][ni], afh[mi], bh);
                    mma_bf16(acc[mi][ni], afh[mi], bl);
                    mma_bf16(acc[mi][ni], afl[mi], bh);
                }
            }
        }
#pragma unroll
        for (int q = 0; q < 4; q++) pf_cur[q] = pf_nxt[q];
    }

    // epilogue: t = acc * schi -> g_t hi/lo
    const int g = lid >> 2, t = lid & 3;
#pragma unroll
    for (int mi = 0; mi < 2; mi++) {
#pragma unroll
        for (int ni = 0; ni < 4; ni++) {
            int row0 = brow + warp_row + mi * 16 + g;
            int row1 = row0 + 8;
            int col  = bn0 + warp_col + ni * 8 + 2 * t;
            const float* a = acc[mi][ni];
            size_t i0 = (size_t)row0 * RANK + col;
            size_t i1 = (size_t)row1 * RANK + col;
            float t00 = a[0] * g_schi[i0], t01 = a[1] * g_schi[i0 + 1];
            float t10 = a[2] * g_schi[i1], t11 = a[3] * g_schi[i1 + 1];
            ushort2 h0, l0, h1, l1;
            split2(t00, h0.x, l0.x); split2(t01, h0.y, l0.y);
            split2(t10, h1.x, l1.x); split2(t11, h1.y, l1.y);
            *(ushort2*)(g_t_hi + i0) = h0; *(ushort2*)(g_t_lo + i0) = l0;
            *(ushort2*)(g_t_hi + i1) = h1; *(ushort2*)(g_t_lo + i1) = l1;
        }
    }
}

// ---------------------------------------------------------------------------
// Launch. Input order:
// 0: inputs [4096,4096]  1: context [4096,512]  2: U [4096,256]  3: S [256]
// 4: V [4096,256]        5: W [512,256]         6: B [256]       7: bias [4096]
// ---------------------------------------------------------------------------
extern "C" void kernel_launch(void* const* d_in, const int* in_sizes, int n_in,
                              void* d_out, int out_size)
{
    const float* inputs  = (const float*)d_in[0];
    const float* context = (const float*)d_in[1];
    const float* U       = (const float*)d_in[2];
    const float* S       = (const float*)d_in[3];
    const float* V       = (const float*)d_in[4];
    const float* W       = (const float*)d_in[5];
    const float* Bvec    = (const float*)d_in[6];
    const float* bias    = (const float*)d_in[7];
    float* out = (float*)d_out;

    const int smem_chi = 4 * (128 + 64) * 160;               // 122880
    const int smem_g2  = 4 * (128 + 128) * 160;              // 163840
    const int smem_g1  = 2 * 20480 + 6 * 10240;              // 102400

    cudaFuncSetAttribute(mma_gemm<128, 64, 4, 2, 512, 0, 4>,
                         cudaFuncAttributeMaxDynamicSharedMemorySize, smem_chi);
    cudaFuncSetAttribute(gemm1_fused,
                         cudaFuncAttributeMaxDynamicSharedMemorySize, smem_g1);
    cudaFuncSetAttribute(mma_gemm<128, 128, 2, 4, 256, 2, 4>,
                         cudaFuncAttributeMaxDynamicSharedMemorySize, smem_g2);

    // launch 0: prep1 (ctx split + W transpose)
    prep1<<<2048 + 128, 256>>>(context, W);
    // launch 1: chi = S*sigmoid(context @ W^T + B)   [4096 x 256], K=512
    mma_gemm<128, 64, 4, 2, 512, 0, 4><<<dim3(RANK / 64, B_SZ / 128), 256, smem_chi>>>(
        nullptr, S, Bvec);
    // launch 2: prep2 (V split + U transpose)
    prep2<<<1024 + 1024, 256>>>(V, U);
    // launch 3 (profiled): gemm1 fused, t = (inputs @ U^T) * schi
    gemm1_fused<<<dim3(RANK / 64, B_SZ / 128), 256, smem_g1>>>(inputs);
    // launch 4: out = relu(t @ V^T + 2*bias)  [4096 x 4096], K=256
    mma_gemm<128, 128, 2, 4, 256, 2, 4><<<dim3(UNITS / 128, B_SZ / 128), 256, smem_g2>>>(
        out, bias, nullptr);
}

// round 11
// speedup vs baseline: 1.2365x; 1.1698x over previous
#include <cuda_runtime.h>
#include <cuda_bf16.h>
#include <cstdint>
#include <math.h>

// Problem dims (fixed)
#define B_SZ   4096
#define N_IN   4096
#define N_CTX  512
#define UNITS  4096
#define RANK   256

// ---------------------------------------------------------------------------
// Device scratch
// ---------------------------------------------------------------------------
__device__ __align__(16) unsigned short g_ctx_hi[B_SZ * N_CTX];
__device__ __align__(16) unsigned short g_ctx_lo[B_SZ * N_CTX];
__device__ __align__(16) unsigned short g_t_hi[B_SZ * RANK];
__device__ __align__(16) unsigned short g_t_lo[B_SZ * RANK];
__device__ __align__(16) unsigned short g_Ut_hi[RANK * N_IN];   // U^T [256][4096]
__device__ __align__(16) unsigned short g_Ut_lo[RANK * N_IN];
__device__ __align__(16) unsigned short g_V_hi[UNITS * RANK];
__device__ __align__(16) unsigned short g_V_lo[UNITS * RANK];
__device__ __align__(16) unsigned short g_Wt_hi[RANK * N_CTX];  // W^T [256][512]
__device__ __align__(16) unsigned short g_Wt_lo[RANK * N_CTX];
__device__ __align__(16) float          g_schi[B_SZ * RANK];
__device__ __align__(16) float          g_part[2][B_SZ * RANK]; // gemm1 K-split partials

// ---------------------------------------------------------------------------
// Helpers
// ---------------------------------------------------------------------------
__device__ __forceinline__ uint32_t smem_to_u32(const void* p) {
    uint32_t a;
    asm("{ .reg .u64 t; cvta.to.shared.u64 t, %1; cvt.u32.u64 %0, t; }"
        : "=r"(a) : "l"(p));
    return a;
}

__device__ __forceinline__ void ldmx4(uint32_t* r, uint32_t addr) {
    asm volatile("ldmatrix.sync.aligned.m8n8.x4.shared.b16 {%0,%1,%2,%3}, [%4];\n"
                 : "=r"(r[0]), "=r"(r[1]), "=r"(r[2]), "=r"(r[3]) : "r"(addr));
}

__device__ __forceinline__ void mma_bf16(float* c, const uint32_t* a, const uint32_t* b) {
    asm volatile(
        "mma.sync.aligned.m16n8k16.row.col.f32.bf16.bf16.f32 "
        "{%0,%1,%2,%3}, {%4,%5,%6,%7}, {%8,%9}, {%0,%1,%2,%3};\n"
        : "+f"(c[0]), "+f"(c[1]), "+f"(c[2]), "+f"(c[3])
        : "r"(a[0]), "r"(a[1]), "r"(a[2]), "r"(a[3]), "r"(b[0]), "r"(b[1]));
}

#define CP_ASYNC16(saddr, gptr) \
    asm volatile("cp.async.cg.shared.global [%0], [%1], 16;\n" \
                 :: "r"(saddr), "l"(gptr))
#define CP_COMMIT() asm volatile("cp.async.commit_group;\n" ::: "memory")

template <int N>
__device__ __forceinline__ void cp_wait_group() {
    asm volatile("cp.async.wait_group %0;\n" :: "n"(N) : "memory");
}

__device__ __forceinline__ void split2(float x, unsigned short& h, unsigned short& l) {
    __nv_bfloat16 hb = __float2bfloat16_rn(x);
    h = *reinterpret_cast<unsigned short*>(&hb);
    float r = x - __bfloat162float(hb);
    __nv_bfloat16 lb = __float2bfloat16_rn(r);
    l = *reinterpret_cast<unsigned short*>(&lb);
}

// ---------------------------------------------------------------------------
// Fused prep kernels
// ---------------------------------------------------------------------------
__global__ __launch_bounds__(256)
void prep1(const float* __restrict__ ctx, const float* __restrict__ W)
{
    __shared__ float tile[32][33];
    int b = blockIdx.x, tid = threadIdx.x;
    if (b < 2048) {
        size_t i = ((size_t)b * 256 + tid) * 4;
        float4 v = *(const float4*)(ctx + i);
        ushort4 h, l;
        split2(v.x, h.x, l.x); split2(v.y, h.y, l.y);
        split2(v.z, h.z, l.z); split2(v.w, h.w, l.w);
        *(ushort4*)(g_ctx_hi + i) = h;
        *(ushort4*)(g_ctx_lo + i) = l;
    } else {
        int bb = b - 2048;                 // W: R=512, C=256
        int c0 = (bb & 7) * 32;
        int r0 = (bb >> 3) * 32;
        int tx = tid & 31, ty = tid >> 5;
        for (int i = ty; i < 32; i += 8)
            tile[i][tx] = W[(size_t)(r0 + i) * RANK + c0 + tx];
        __syncthreads();
        for (int i = ty; i < 32; i += 8) {
            int c = c0 + i, r = r0 + tx;
            unsigned short h, l;
            split2(tile[tx][i], h, l);
            g_Wt_hi[(size_t)c * N_CTX + r] = h;
            g_Wt_lo[(size_t)c * N_CTX + r] = l;
        }
    }
}

__global__ __launch_bounds__(256)
void prep2(const float* __restrict__ V, const float* __restrict__ U)
{
    __shared__ float tile[32][33];
    int b = blockIdx.x, tid = threadIdx.x;
    if (b < 1024) {
        size_t i = ((size_t)b * 256 + tid) * 4;
        float4 v = *(const float4*)(V + i);
        ushort4 h, l;
        split2(v.x, h.x, l.x); split2(v.y, h.y, l.y);
        split2(v.z, h.z, l.z); split2(v.w, h.w, l.w);
        *(ushort4*)(g_V_hi + i) = h;
        *(ushort4*)(g_V_lo + i) = l;
    } else {
        int bb = b - 1024;                 // U: R=4096, C=256
        int c0 = (bb & 7) * 32;
        int r0 = (bb >> 3) * 32;
        int tx = tid & 31, ty = tid >> 5;
        for (int i = ty; i < 32; i += 8)
            tile[i][tx] = U[(size_t)(r0 + i) * RANK + c0 + tx];
        __syncthreads();
        for (int i = ty; i < 32; i += 8) {
            int c = c0 + i, r = r0 + tx;
            unsigned short h, l;
            split2(tile[tx][i], h, l);
            g_Ut_hi[(size_t)c * N_IN + r] = h;
            g_Ut_lo[(size_t)c * N_IN + r] = l;
        }
    }
}

// ---------------------------------------------------------------------------
// Template GEMM (pre-split A). EPI 0 (chi) and 2 (out).
// ---------------------------------------------------------------------------
template <int TILEM, int TILEN, int WARPS_M, int WARPS_N, int KTOT, int EPI,
          int STAGES, int MINCTA>
__global__ __launch_bounds__(WARPS_M * WARPS_N * 32, MINCTA)
void mma_gemm(float* __restrict__ outp,
              const float* __restrict__ ev0,   // EPI0: S, EPI2: bias
              const float* __restrict__ ev1)   // EPI0: Bvec
{
    constexpr int THREADS = WARPS_M * WARPS_N * 32;
    constexpr int WM = TILEM / WARPS_M;
    constexpr int MI = WM / 16;
    constexpr int NI = 4;
    constexpr int AHB = TILEM * 40 * 2;
    constexpr int BHB = TILEN * 40 * 2;
    constexpr int STG = 2 * AHB + 2 * BHB;
    constexpr int NC  = KTOT / 32;
    constexpr int A_IT = TILEM * 4 / THREADS;
    constexpr int B_IT = TILEN * 4 / THREADS;
    static_assert(WARPS_N * 32 == TILEN, "tile mismatch");

    extern __shared__ char smem[];
    const uint32_t sb = smem_to_u32(smem);

    const int tid = threadIdx.x;
    const int wid = tid >> 5, lid = tid & 31;
    const int wm = wid / WARPS_N, wn = wid % WARPS_N;
    const int warp_row = wm * WM;
    const int warp_col = wn * 32;
    const int brow = blockIdx.y * TILEM;
    const int bn0  = blockIdx.x * TILEN;

    const unsigned short* Ahg = (EPI == 0) ? g_ctx_hi : g_t_hi;
    const unsigned short* Alg = (EPI == 0) ? g_ctx_lo : g_t_lo;
    const unsigned short* Bhg = (EPI == 0) ? g_Wt_hi : g_V_hi;
    const unsigned short* Blg = (EPI == 0) ? g_Wt_lo : g_V_lo;

    float acc[MI][NI][4];
#pragma unroll
    for (int mi = 0; mi < MI; mi++)
#pragma unroll
        for (int ni = 0; ni < NI; ni++)
#pragma unroll
            for (int q = 0; q < 4; q++) acc[mi][ni][q] = 0.f;

    const uint32_t a_lane = (uint32_t)(((lid & 15) * 40 + (lid >> 4) * 8) * 2);
    const uint32_t b_lane = (uint32_t)((((lid & 7) + ((lid >> 4) << 3)) * 40 +
                                        ((lid >> 3) & 1) * 8) * 2);

    auto load_stage = [&](int s, int k0) {
        const uint32_t st = sb + (uint32_t)(s * STG);
#pragma unroll
        for (int it = 0; it < A_IT; it++) {
            int flat = it * THREADS + tid;
            int row = flat >> 2, seg = flat & 3;
            uint32_t off = (uint32_t)(row * 80 + seg * 16);
            size_t gi = (size_t)(brow + row) * KTOT + k0 + seg * 8;
            CP_ASYNC16(st + off, Ahg + gi);
            CP_ASYNC16(st + AHB + off, Alg + gi);
        }
#pragma unroll
        for (int it = 0; it < B_IT; it++) {
            int flat = it * THREADS + tid;
            int row = flat >> 2, seg = flat & 3;
            uint32_t off = (uint32_t)(row * 80 + seg * 16);
            size_t gi = (size_t)(bn0 + row) * KTOT + k0 + seg * 8;
            CP_ASYNC16(st + 2 * AHB + off, Bhg + gi);
            CP_ASYNC16(st + 2 * AHB + BHB + off, Blg + gi);
        }
    };

#pragma unroll
    for (int s = 0; s < STAGES - 1; s++) {
        load_stage(s, s * 32);
        CP_COMMIT();
    }

    for (int ch = 0; ch < NC; ch++) {
        cp_wait_group<STAGES - 2>();
        __syncthreads();

        if (ch + STAGES - 1 < NC)
            load_stage((ch + STAGES - 1) % STAGES, (ch + STAGES - 1) * 32);
        CP_COMMIT();

        const uint32_t cb = sb + (uint32_t)((ch % STAGES) * STG);
        const uint32_t Ah = cb, Al = cb + AHB, Bh = cb + 2 * AHB, Bl = Bh + BHB;
#pragma unroll
        for (int ks = 0; ks < 2; ks++) {
            uint32_t afh[MI][4], afl[MI][4], bfh[2][4], bfl[2][4];
#pragma unroll
            for (int mi = 0; mi < MI; mi++) {
                uint32_t ao = a_lane + (uint32_t)((warp_row + mi * 16) * 80 + ks * 32);
                ldmx4(afh[mi], Ah + ao);
                ldmx4(afl[mi], Al + ao);
            }
#pragma unroll
            for (int j = 0; j < 2; j++) {
                uint32_t bo = b_lane + (uint32_t)((warp_col + j * 16) * 80 + ks * 32);
                ldmx4(bfh[j], Bh + bo);
                ldmx4(bfl[j], Bl + bo);
            }
#pragma unroll
            for (int mi = 0; mi < MI; mi++) {
#pragma unroll
                for (int ni = 0; ni < NI; ni++) {
                    const uint32_t* bh = &bfh[ni >> 1][(ni & 1) * 2];
                    const uint32_t* bl = &bfl[ni >> 1][(ni & 1) * 2];
                    mma_bf16(acc[mi][ni], afh[mi], bh);
                    mma_bf16(acc[mi][ni], afh[mi], bl);
                    mma_bf16(acc[mi][ni], afl[mi], bh);
                }
            }
        }
    }

    const int g = lid >> 2, t = lid & 3;
#pragma unroll
    for (int mi = 0; mi < MI; mi++) {
#pragma unroll
        for (int ni = 0; ni < NI; ni++) {
            int row0 = brow + warp_row + mi * 16 + g;
            int row1 = row0 + 8;
            int col  = bn0 + warp_col + ni * 8 + 2 * t;
            const float* a = acc[mi][ni];
            if (EPI == 0) {
                float bv0 = ev1[col], bv1 = ev1[col + 1];
                float s0 = ev0[col], s1 = ev0[col + 1];
                float x00 = a[0] + bv0, x01 = a[1] + bv1;
                float x10 = a[2] + bv0, x11 = a[3] + bv1;
                float2 r0 = make_float2(s0 / (1.f + expf(-x00)), s1 / (1.f + expf(-x01)));
                float2 r1 = make_float2(s0 / (1.f + expf(-x10)), s1 / (1.f + expf(-x11)));
                *(float2*)(g_schi + (size_t)row0 * RANK + col) = r0;
                *(float2*)(g_schi + (size_t)row1 * RANK + col) = r1;
            } else {
                float b0 = 2.f * ev0[col], b1 = 2.f * ev0[col + 1];
                float2 r0 = make_float2(fmaxf(a[0] + b0, 0.f), fmaxf(a[1] + b1, 0.f));
                float2 r1 = make_float2(fmaxf(a[2] + b0, 0.f), fmaxf(a[3] + b1, 0.f));
                *(float2*)(outp + (size_t)row0 * UNITS + col) = r0;
                *(float2*)(outp + (size_t)row1 * UNITS + col) = r1;
            }
        }
    }
}

// ---------------------------------------------------------------------------
// GEMM1 fused, K-split x2: partial = inputs[:, ks*2048:(ks+1)*2048] @ U^T slice
//   128x64 tile, 256 threads, grid (4, 32, 2). fp32 partials to g_part[ks].
//   A: LDG fp32 one chunk ahead -> convert -> STS (2 smem stages)
//   B: 6-stage cp.async of pre-split U^T hi/lo
// ---------------------------------------------------------------------------
__global__ __launch_bounds__(256, 2)
void gemm1_fused(const float* __restrict__ Afp)
{
    constexpr int KTOT = N_IN;
    constexpr int KSEG = KTOT / 2;       // 2048 per split
    constexpr int NC = KSEG / 32;        // 64
    constexpr int AHB = 128 * 40 * 2;    // 10240
    constexpr int ABUF = 2 * AHB;        // 20480
    constexpr int BHB = 64 * 40 * 2;     // 5120
    constexpr int BSTG = 2 * BHB;        // 10240
    constexpr int BSTAGES = 6;

    extern __shared__ char smem[];
    const uint32_t sb = smem_to_u32(smem);
    const uint32_t sbB = sb + 2 * ABUF;

    const int tid = threadIdx.x;
    const int wid = tid >> 5, lid = tid & 31;
    const int wm = wid >> 1, wn = wid & 1;  // 4x2 warps
    const int warp_row = wm * 32;
    const int warp_col = wn * 32;
    const int brow = blockIdx.y * 128;
    const int bn0  = blockIdx.x * 64;
    const int kseg = blockIdx.z;
    const int koff = kseg * KSEG;

    float acc[2][4][4];
#pragma unroll
    for (int mi = 0; mi < 2; mi++)
#pragma unroll
        for (int ni = 0; ni < 4; ni++)
#pragma unroll
            for (int q = 0; q < 4; q++) acc[mi][ni][q] = 0.f;

    const uint32_t a_lane = (uint32_t)(((lid & 15) * 40 + (lid >> 4) * 8) * 2);
    const uint32_t b_lane = (uint32_t)((((lid & 7) + ((lid >> 4) << 3)) * 40 +
                                        ((lid >> 3) & 1) * 8) * 2);

    auto ldgA = [&](int k0, float4* pf) {
#pragma unroll
        for (int it = 0; it < 4; it++) {
            int flat = it * 256 + tid;
            int row = flat >> 3, seg = flat & 7;
            pf[it] = *(const float4*)(Afp + (size_t)(brow + row) * KTOT + k0 + seg * 4);
        }
    };
    auto cvtA = [&](int s, const float4* pf) {
        uint32_t base = (uint32_t)(s * ABUF);
#pragma unroll
        for (int it = 0; it < 4; it++) {
            int flat = it * 256 + tid;
            int row = flat >> 3, seg = flat & 7;
            ushort4 h, l;
            split2(pf[it].x, h.x, l.x);
            split2(pf[it].y, h.y, l.y);
            split2(pf[it].z, h.z, l.z);
            split2(pf[it].w, h.w, l.w);
            uint32_t off = base + (uint32_t)(row * 80 + seg * 8);
            *(ushort4*)(smem + off) = h;
            *(ushort4*)(smem + off + AHB) = l;
        }
    };
    auto loadB = [&](int s, int k0) {
        uint32_t st = sbB + (uint32_t)(s * BSTG);
        int row = tid >> 2, seg = tid & 3;
        uint32_t off = (uint32_t)(row * 80 + seg * 16);
        size_t gi = (size_t)(bn0 + row) * KTOT + k0 + seg * 8;
        CP_ASYNC16(st + off, g_Ut_hi + gi);
        CP_ASYNC16(st + BHB + off, g_Ut_lo + gi);
    };

    // prologue
    float4 pf_cur[4], pf_nxt[4];
    ldgA(koff, pf_cur);
    cvtA(0, pf_cur);
    ldgA(koff + 32, pf_cur);
#pragma unroll
    for (int s = 0; s < BSTAGES - 1; s++) {
        loadB(s, koff + s * 32);
        CP_COMMIT();
    }

    for (int ch = 0; ch < NC; ch++) {
        cp_wait_group<BSTAGES - 2>();
        __syncthreads();

        if (ch + 2 < NC) ldgA(koff + (ch + 2) * 32, pf_nxt);
        if (ch + 1 < NC) cvtA((ch + 1) & 1, pf_cur);
        if (ch + BSTAGES - 1 < NC)
            loadB((ch + BSTAGES - 1) % BSTAGES, koff + (ch + BSTAGES - 1) * 32);
        CP_COMMIT();

        const uint32_t Ah = sb + (uint32_t)((ch & 1) * ABUF);
        const uint32_t Al = Ah + AHB;
        const uint32_t Bh = sbB + (uint32_t)((ch % BSTAGES) * BSTG);
        const uint32_t Bl = Bh + BHB;
#pragma unroll
        for (int ks = 0; ks < 2; ks++) {
            uint32_t afh[2][4], afl[2][4], bfh[2][4], bfl[2][4];
#pragma unroll
            for (int mi = 0; mi < 2; mi++) {
                uint32_t ao = a_lane + (uint32_t)((warp_row + mi * 16) * 80 + ks * 32);
                ldmx4(afh[mi], Ah + ao);
                ldmx4(afl[mi], Al + ao);
            }
#pragma unroll
            for (int j = 0; j < 2; j++) {
                uint32_t bo = b_lane + (uint32_t)((warp_col + j * 16) * 80 + ks * 32);
                ldmx4(bfh[j], Bh + bo);
                ldmx4(bfl[j], Bl + bo);
            }
#pragma unroll
            for (int mi = 0; mi < 2; mi++) {
#pragma unroll
                for (int ni = 0; ni < 4; ni++) {
                    const uint32_t* bh = &bfh[ni >> 1][(ni & 1) * 2];
                    const uint32_t* bl = &bfl[ni >> 1][(ni & 1) * 2];
                    mma_bf16(acc[mi][ni], afh[mi], bh);
                    mma_bf16(acc[mi][ni], afh[mi], bl);
                    mma_bf16(acc[mi][ni], afl[mi], bh);
                }
            }
        }
#pragma unroll
        for (int q = 0; q < 4; q++) pf_cur[q] = pf_nxt[q];
    }

    // epilogue: fp32 partial -> g_part[kseg]
    float* dst = &g_part[kseg][0];
    const int g = lid >> 2, t = lid & 3;
#pragma unroll
    for (int mi = 0; mi < 2; mi++) {
#pragma unroll
        for (int ni = 0; ni < 4; ni++) {
            int row0 = brow + warp_row + mi * 16 + g;
            int row1 = row0 + 8;
            int col  = bn0 + warp_col + ni * 8 + 2 * t;
            const float* a = acc[mi][ni];
            *(float2*)(dst + (size_t)row0 * RANK + col) = make_float2(a[0], a[1]);
            *(float2*)(dst + (size_t)row1 * RANK + col) = make_float2(a[2], a[3]);
        }
    }
}

// ---------------------------------------------------------------------------
// k_finish: t = (p0 + p1) * schi -> g_t hi/lo
// ---------------------------------------------------------------------------
__global__ __launch_bounds__(256)
void k_finish()
{
    size_t i = ((size_t)blockIdx.x * 256 + threadIdx.x) * 4;
    float4 p0 = *(const float4*)(&g_part[0][i]);
    float4 p1 = *(const float4*)(&g_part[1][i]);
    float4 sc = *(const float4*)(g_schi + i);
    float4 t;
    t.x = (p0.x + p1.x) * sc.x;
    t.y = (p0.y + p1.y) * sc.y;
    t.z = (p0.z + p1.z) * sc.z;
    t.w = (p0.w + p1.w) * sc.w;
    ushort4 h, l;
    split2(t.x, h.x, l.x);
    split2(t.y, h.y, l.y);
    split2(t.z, h.z, l.z);
    split2(t.w, h.w, l.w);
    *(ushort4*)(g_t_hi + i) = h;
    *(ushort4*)(g_t_lo + i) = l;
}

// ---------------------------------------------------------------------------
// Launch. Input order:
// 0: inputs [4096,4096]  1: context [4096,512]  2: U [4096,256]  3: S [256]
// 4: V [4096,256]        5: W [512,256]         6: B [256]       7: bias [4096]
// ---------------------------------------------------------------------------
extern "C" void kernel_launch(void* const* d_in, const int* in_sizes, int n_in,
                              void* d_out, int out_size)
{
    const float* inputs  = (const float*)d_in[0];
    const float* context = (const float*)d_in[1];
    const float* U       = (const float*)d_in[2];
    const float* S       = (const float*)d_in[3];
    const float* V       = (const float*)d_in[4];
    const float* W       = (const float*)d_in[5];
    const float* Bvec    = (const float*)d_in[6];
    const float* bias    = (const float*)d_in[7];
    float* out = (float*)d_out;

    const int smem_chi = 4 * (128 + 64) * 160;      // 122880
    const int smem_g1  = 2 * 20480 + 6 * 10240;     // 102400 -> 2 CTAs/SM
    const int smem_g2  = 2 * (128 + 128) * 160;     // 81920  -> 2 CTAs/SM

    cudaFuncSetAttribute(mma_gemm<128, 64, 4, 2, 512, 0, 4, 1>,
                         cudaFuncAttributeMaxDynamicSharedMemorySize, smem_chi);
    cudaFuncSetAttribute(gemm1_fused,
                         cudaFuncAttributeMaxDynamicSharedMemorySize, smem_g1);
    cudaFuncSetAttribute(mma_gemm<128, 128, 2, 4, 256, 2, 2, 2>,
                         cudaFuncAttributeMaxDynamicSharedMemorySize, smem_g2);

    // launch 0: prep1 (ctx split + W transpose)
    prep1<<<2048 + 128, 256>>>(context, W);
    // launch 1: chi = S*sigmoid(context @ W^T + B)
    mma_gemm<128, 64, 4, 2, 512, 0, 4, 1><<<dim3(RANK / 64, B_SZ / 128), 256, smem_chi>>>(
        nullptr, S, Bvec);
    // launch 2: prep2 (V split + U transpose)
    prep2<<<1024 + 1024, 256>>>(V, U);
    // launch 3 (profiled): gemm1 K-split x2, grid 256 CTAs
    gemm1_fused<<<dim3(RANK / 64, B_SZ / 128, 2), 256, smem_g1>>>(inputs);
    // launch 4: finish (reduce partials, scale by schi, split to bf16)
    k_finish<<<(B_SZ * RANK) / 1024, 256>>>();
    // launch 5: out = relu(t @ V^T + 2*bias), 2 CTAs/SM
    mma_gemm<128, 128, 2, 4, 256, 2, 2, 2><<<dim3(UNITS / 128, B_SZ / 128), 256, smem_g2>>>(
        out, bias, nullptr);
}

// round 12
// speedup vs baseline: 1.2616x; 1.0202x over previous
#include <cuda_runtime.h>
#include <cuda_bf16.h>
#include <cstdint>
#include <math.h>

// Problem dims (fixed)
#define B_SZ   4096
#define N_IN   4096
#define N_CTX  512
#define UNITS  4096
#define RANK   256

// ---------------------------------------------------------------------------
// Device scratch
// ---------------------------------------------------------------------------
__device__ __align__(16) unsigned short g_ctx_hi[B_SZ * N_CTX];
__device__ __align__(16) unsigned short g_ctx_lo[B_SZ * N_CTX];
__device__ __align__(16) unsigned short g_t_hi[B_SZ * RANK];
__device__ __align__(16) unsigned short g_t_lo[B_SZ * RANK];
__device__ __align__(16) unsigned short g_Ut_hi[RANK * N_IN];   // U^T [256][4096]
__device__ __align__(16) unsigned short g_Ut_lo[RANK * N_IN];
__device__ __align__(16) unsigned short g_V_hi[UNITS * RANK];
__device__ __align__(16) unsigned short g_V_lo[UNITS * RANK];
__device__ __align__(16) unsigned short g_Wt_hi[RANK * N_CTX];  // W^T [256][512]
__device__ __align__(16) unsigned short g_Wt_lo[RANK * N_CTX];
__device__ __align__(16) float          g_schi[B_SZ * RANK];
__device__ __align__(16) float          g_part[2][B_SZ * RANK];

// ---------------------------------------------------------------------------
// Helpers
// ---------------------------------------------------------------------------
__device__ __forceinline__ uint32_t smem_to_u32(const void* p) {
    uint32_t a;
    asm("{ .reg .u64 t; cvta.to.shared.u64 t, %1; cvt.u32.u64 %0, t; }"
        : "=r"(a) : "l"(p));
    return a;
}

__device__ __forceinline__ void ldmx4(uint32_t* r, uint32_t addr) {
    asm volatile("ldmatrix.sync.aligned.m8n8.x4.shared.b16 {%0,%1,%2,%3}, [%4];\n"
                 : "=r"(r[0]), "=r"(r[1]), "=r"(r[2]), "=r"(r[3]) : "r"(addr));
}

__device__ __forceinline__ void mma_bf16(float* c, const uint32_t* a, const uint32_t* b) {
    asm volatile(
        "mma.sync.aligned.m16n8k16.row.col.f32.bf16.bf16.f32 "
        "{%0,%1,%2,%3}, {%4,%5,%6,%7}, {%8,%9}, {%0,%1,%2,%3};\n"
        : "+f"(c[0]), "+f"(c[1]), "+f"(c[2]), "+f"(c[3])
        : "r"(a[0]), "r"(a[1]), "r"(a[2]), "r"(a[3]), "r"(b[0]), "r"(b[1]));
}

#define CP_ASYNC16(saddr, gptr) \
    asm volatile("cp.async.cg.shared.global [%0], [%1], 16;\n" \
                 :: "r"(saddr), "l"(gptr))
#define CP_COMMIT() asm volatile("cp.async.commit_group;\n" ::: "memory")

template <int N>
__device__ __forceinline__ void cp_wait_group() {
    asm volatile("cp.async.wait_group %0;\n" :: "n"(N) : "memory");
}

__device__ __forceinline__ void split2(float x, unsigned short& h, unsigned short& l) {
    __nv_bfloat16 hb = __float2bfloat16_rn(x);
    h = *reinterpret_cast<unsigned short*>(&hb);
    float r = x - __bfloat162float(hb);
    __nv_bfloat16 lb = __float2bfloat16_rn(r);
    l = *reinterpret_cast<unsigned short*>(&lb);
}

// ---------------------------------------------------------------------------
// Fused prep kernels
// ---------------------------------------------------------------------------
__global__ __launch_bounds__(256)
void prep1(const float* __restrict__ ctx, const float* __restrict__ W)
{
    __shared__ float tile[32][33];
    int b = blockIdx.x, tid = threadIdx.x;
    if (b < 2048) {
        size_t i = ((size_t)b * 256 + tid) * 4;
        float4 v = *(const float4*)(ctx + i);
        ushort4 h, l;
        split2(v.x, h.x, l.x); split2(v.y, h.y, l.y);
        split2(v.z, h.z, l.z); split2(v.w, h.w, l.w);
        *(ushort4*)(g_ctx_hi + i) = h;
        *(ushort4*)(g_ctx_lo + i) = l;
    } else {
        int bb = b - 2048;
        int c0 = (bb & 7) * 32;
        int r0 = (bb >> 3) * 32;
        int tx = tid & 31, ty = tid >> 5;
        for (int i = ty; i < 32; i += 8)
            tile[i][tx] = W[(size_t)(r0 + i) * RANK + c0 + tx];
        __syncthreads();
        for (int i = ty; i < 32; i += 8) {
            int c = c0 + i, r = r0 + tx;
            unsigned short h, l;
            split2(tile[tx][i], h, l);
            g_Wt_hi[(size_t)c * N_CTX + r] = h;
            g_Wt_lo[(size_t)c * N_CTX + r] = l;
        }
    }
}

__global__ __launch_bounds__(256)
void prep2(const float* __restrict__ V, const float* __restrict__ U)
{
    __shared__ float tile[32][33];
    int b = blockIdx.x, tid = threadIdx.x;
    if (b < 1024) {
        size_t i = ((size_t)b * 256 + tid) * 4;
        float4 v = *(const float4*)(V + i);
        ushort4 h, l;
        split2(v.x, h.x, l.x); split2(v.y, h.y, l.y);
        split2(v.z, h.z, l.z); split2(v.w, h.w, l.w);
        *(ushort4*)(g_V_hi + i) = h;
        *(ushort4*)(g_V_lo + i) = l;
    } else {
        int bb = b - 1024;
        int c0 = (bb & 7) * 32;
        int r0 = (bb >> 3) * 32;
        int tx = tid & 31, ty = tid >> 5;
        for (int i = ty; i < 32; i += 8)
            tile[i][tx] = U[(size_t)(r0 + i) * RANK + c0 + tx];
        __syncthreads();
        for (int i = ty; i < 32; i += 8) {
            int c = c0 + i, r = r0 + tx;
            unsigned short h, l;
            split2(tile[tx][i], h, l);
            g_Ut_hi[(size_t)c * N_IN + r] = h;
            g_Ut_lo[(size_t)c * N_IN + r] = l;
        }
    }
}

// ---------------------------------------------------------------------------
// Template GEMM (pre-split A). EPI 0 (chi) and 2 (out).
// ---------------------------------------------------------------------------
template <int TILEM, int TILEN, int WARPS_M, int WARPS_N, int KTOT, int EPI,
          int STAGES, int MINCTA>
__global__ __launch_bounds__(WARPS_M * WARPS_N * 32, MINCTA)
void mma_gemm(float* __restrict__ outp,
              const float* __restrict__ ev0,   // EPI0: S, EPI2: bias
              const float* __restrict__ ev1)   // EPI0: Bvec
{
    constexpr int THREADS = WARPS_M * WARPS_N * 32;
    constexpr int WM = TILEM / WARPS_M;
    constexpr int MI = WM / 16;
    constexpr int NI = 4;
    constexpr int AHB = TILEM * 40 * 2;
    constexpr int BHB = TILEN * 40 * 2;
    constexpr int STG = 2 * AHB + 2 * BHB;
    constexpr int NC  = KTOT / 32;
    constexpr int A_IT = TILEM * 4 / THREADS;
    constexpr int B_IT = TILEN * 4 / THREADS;
    static_assert(WARPS_N * 32 == TILEN, "tile mismatch");

    extern __shared__ char smem[];
    const uint32_t sb = smem_to_u32(smem);

    const int tid = threadIdx.x;
    const int wid = tid >> 5, lid = tid & 31;
    const int wm = wid / WARPS_N, wn = wid % WARPS_N;
    const int warp_row = wm * WM;
    const int warp_col = wn * 32;
    const int brow = blockIdx.y * TILEM;
    const int bn0  = blockIdx.x * TILEN;

    const unsigned short* Ahg = (EPI == 0) ? g_ctx_hi : g_t_hi;
    const unsigned short* Alg = (EPI == 0) ? g_ctx_lo : g_t_lo;
    const unsigned short* Bhg = (EPI == 0) ? g_Wt_hi : g_V_hi;
    const unsigned short* Blg = (EPI == 0) ? g_Wt_lo : g_V_lo;

    float acc[MI][NI][4];
#pragma unroll
    for (int mi = 0; mi < MI; mi++)
#pragma unroll
        for (int ni = 0; ni < NI; ni++)
#pragma unroll
            for (int q = 0; q < 4; q++) acc[mi][ni][q] = 0.f;

    const uint32_t a_lane = (uint32_t)(((lid & 15) * 40 + (lid >> 4) * 8) * 2);
    const uint32_t b_lane = (uint32_t)((((lid & 7) + ((lid >> 4) << 3)) * 40 +
                                        ((lid >> 3) & 1) * 8) * 2);

    auto load_stage = [&](int s, int k0) {
        const uint32_t st = sb + (uint32_t)(s * STG);
#pragma unroll
        for (int it = 0; it < A_IT; it++) {
            int flat = it * THREADS + tid;
            int row = flat >> 2, seg = flat & 3;
            uint32_t off = (uint32_t)(row * 80 + seg * 16);
            size_t gi = (size_t)(brow + row) * KTOT + k0 + seg * 8;
            CP_ASYNC16(st + off, Ahg + gi);
            CP_ASYNC16(st + AHB + off, Alg + gi);
        }
#pragma unroll
        for (int it = 0; it < B_IT; it++) {
            int flat = it * THREADS + tid;
            int row = flat >> 2, seg = flat & 3;
            uint32_t off = (uint32_t)(row * 80 + seg * 16);
            size_t gi = (size_t)(bn0 + row) * KTOT + k0 + seg * 8;
            CP_ASYNC16(st + 2 * AHB + off, Bhg + gi);
            CP_ASYNC16(st + 2 * AHB + BHB + off, Blg + gi);
        }
    };

#pragma unroll
    for (int s = 0; s < STAGES - 1; s++) {
        load_stage(s, s * 32);
        CP_COMMIT();
    }

    for (int ch = 0; ch < NC; ch++) {
        cp_wait_group<STAGES - 2>();
        __syncthreads();

        if (ch + STAGES - 1 < NC)
            load_stage((ch + STAGES - 1) % STAGES, (ch + STAGES - 1) * 32);
        CP_COMMIT();

        const uint32_t cb = sb + (uint32_t)((ch % STAGES) * STG);
        const uint32_t Ah = cb, Al = cb + AHB, Bh = cb + 2 * AHB, Bl = Bh + BHB;
#pragma unroll
        for (int ks = 0; ks < 2; ks++) {
            uint32_t afh[MI][4], afl[MI][4], bfh[2][4], bfl[2][4];
#pragma unroll
            for (int mi = 0; mi < MI; mi++) {
                uint32_t ao = a_lane + (uint32_t)((warp_row + mi * 16) * 80 + ks * 32);
                ldmx4(afh[mi], Ah + ao);
                ldmx4(afl[mi], Al + ao);
            }
#pragma unroll
            for (int j = 0; j < 2; j++) {
                uint32_t bo = b_lane + (uint32_t)((warp_col + j * 16) * 80 + ks * 32);
                ldmx4(bfh[j], Bh + bo);
                ldmx4(bfl[j], Bl + bo);
            }
#pragma unroll
            for (int mi = 0; mi < MI; mi++) {
#pragma unroll
                for (int ni = 0; ni < NI; ni++) {
                    const uint32_t* bh = &bfh[ni >> 1][(ni & 1) * 2];
                    const uint32_t* bl = &bfl[ni >> 1][(ni & 1) * 2];
                    mma_bf16(acc[mi][ni], afh[mi], bh);
                    mma_bf16(acc[mi][ni], afh[mi], bl);
                    mma_bf16(acc[mi][ni], afl[mi], bh);
                }
            }
        }
    }

    const int g = lid >> 2, t = lid & 3;
#pragma unroll
    for (int mi = 0; mi < MI; mi++) {
#pragma unroll
        for (int ni = 0; ni < NI; ni++) {
            int row0 = brow + warp_row + mi * 16 + g;
            int row1 = row0 + 8;
            int col  = bn0 + warp_col + ni * 8 + 2 * t;
            const float* a = acc[mi][ni];
            if (EPI == 0) {
                float bv0 = ev1[col], bv1 = ev1[col + 1];
                float s0 = ev0[col], s1 = ev0[col + 1];
                float x00 = a[0] + bv0, x01 = a[1] + bv1;
                float x10 = a[2] + bv0, x11 = a[3] + bv1;
                float2 r0 = make_float2(s0 / (1.f + expf(-x00)), s1 / (1.f + expf(-x01)));
                float2 r1 = make_float2(s0 / (1.f + expf(-x10)), s1 / (1.f + expf(-x11)));
                *(float2*)(g_schi + (size_t)row0 * RANK + col) = r0;
                *(float2*)(g_schi + (size_t)row1 * RANK + col) = r1;
            } else {
                float b0 = 2.f * ev0[col], b1 = 2.f * ev0[col + 1];
                float2 r0 = make_float2(fmaxf(a[0] + b0, 0.f), fmaxf(a[1] + b1, 0.f));
                float2 r1 = make_float2(fmaxf(a[2] + b0, 0.f), fmaxf(a[3] + b1, 0.f));
                *(float2*)(outp + (size_t)row0 * UNITS + col) = r0;
                *(float2*)(outp + (size_t)row1 * UNITS + col) = r1;
            }
        }
    }
}

// ---------------------------------------------------------------------------
// GEMM1 fused v2: 64x128 tile, 128 threads (1x4 warps), WM=64 (MI=4).
//   K-split x2 via blockIdx.z -> fp32 partials.
//   A: LDG fp32 one chunk ahead -> convert -> STS (2 smem stages)
//   B: 4-stage cp.async of pre-split U^T hi/lo
//   12 ldmatrix per 48 MMAs (1:4) vs prior 1:3 — 25% less smem read traffic.
// ---------------------------------------------------------------------------
__global__ __launch_bounds__(128, 2)
void gemm1_fused(const float* __restrict__ Afp)
{
    constexpr int KTOT = N_IN;
    constexpr int KSEG = KTOT / 2;       // 2048
    constexpr int NC = KSEG / 32;        // 64
    constexpr int AHB = 64 * 40 * 2;     // 5120 (one half per stage)
    constexpr int ABUF = 2 * AHB;        // 10240
    constexpr int BHB = 128 * 40 * 2;    // 10240
    constexpr int BSTG = 2 * BHB;        // 20480
    constexpr int BSTAGES = 4;
    // smem: A 2*ABUF = 20480 ; B 4*BSTG = 81920 ; total 102400 -> 2 CTAs/SM

    extern __shared__ char smem[];
    const uint32_t sb = smem_to_u32(smem);
    const uint32_t sbB = sb + 2 * ABUF;

    const int tid = threadIdx.x;
    const int wid = tid >> 5, lid = tid & 31;
    const int wn = wid;                     // 1x4 warps: wm=0
    const int warp_col = wn * 32;
    const int brow = blockIdx.y * 64;
    const int bn0  = blockIdx.x * 128;
    const int kseg = blockIdx.z;
    const int koff = kseg * KSEG;

    float acc[4][4][4];
#pragma unroll
    for (int mi = 0; mi < 4; mi++)
#pragma unroll
        for (int ni = 0; ni < 4; ni++)
#pragma unroll
            for (int q = 0; q < 4; q++) acc[mi][ni][q] = 0.f;

    const uint32_t a_lane = (uint32_t)(((lid & 15) * 40 + (lid >> 4) * 8) * 2);
    const uint32_t b_lane = (uint32_t)((((lid & 7) + ((lid >> 4) << 3)) * 40 +
                                        ((lid >> 3) & 1) * 8) * 2);

    auto ldgA = [&](int k0, float4* pf) {
#pragma unroll
        for (int it = 0; it < 4; it++) {
            int flat = it * 128 + tid;      // 64 rows x 8 segs = 512 tasks
            int row = flat >> 3, seg = flat & 7;
            pf[it] = *(const float4*)(Afp + (size_t)(brow + row) * KTOT + k0 + seg * 4);
        }
    };
    auto cvtA = [&](int s, const float4* pf) {
        uint32_t base = (uint32_t)(s * ABUF);
#pragma unroll
        for (int it = 0; it < 4; it++) {
            int flat = it * 128 + tid;
            int row = flat >> 3, seg = flat & 7;
            ushort4 h, l;
            split2(pf[it].x, h.x, l.x);
            split2(pf[it].y, h.y, l.y);
            split2(pf[it].z, h.z, l.z);
            split2(pf[it].w, h.w, l.w);
            uint32_t off = base + (uint32_t)(row * 80 + seg * 8);
            *(ushort4*)(smem + off) = h;
            *(ushort4*)(smem + off + AHB) = l;
        }
    };
    auto loadB = [&](int s, int k0) {
        uint32_t st = sbB + (uint32_t)(s * BSTG);
#pragma unroll
        for (int it = 0; it < 4; it++) {
            int flat = it * 128 + tid;      // 128 rows x 4 segs = 512 tasks
            int row = flat >> 2, seg = flat & 3;
            uint32_t off = (uint32_t)(row * 80 + seg * 16);
            size_t gi = (size_t)(bn0 + row) * KTOT + k0 + seg * 8;
            CP_ASYNC16(st + off, g_Ut_hi + gi);
            CP_ASYNC16(st + BHB + off, g_Ut_lo + gi);
        }
    };

    // prologue
    float4 pf_cur[4], pf_nxt[4];
    ldgA(koff, pf_cur);
    cvtA(0, pf_cur);
    ldgA(koff + 32, pf_cur);
#pragma unroll
    for (int s = 0; s < BSTAGES - 1; s++) {
        loadB(s, koff + s * 32);
        CP_COMMIT();
    }

    for (int ch = 0; ch < NC; ch++) {
        cp_wait_group<BSTAGES - 2>();
        __syncthreads();

        if (ch + 2 < NC) ldgA(koff + (ch + 2) * 32, pf_nxt);
        if (ch + 1 < NC) cvtA((ch + 1) & 1, pf_cur);
        if (ch + BSTAGES - 1 < NC)
            loadB((ch + BSTAGES - 1) % BSTAGES, koff + (ch + BSTAGES - 1) * 32);
        CP_COMMIT();

        const uint32_t Ah = sb + (uint32_t)((ch & 1) * ABUF);
        const uint32_t Al = Ah + AHB;
        const uint32_t Bh = sbB + (uint32_t)((ch % BSTAGES) * BSTG);
        const uint32_t Bl = Bh + BHB;
#pragma unroll
        for (int ks = 0; ks < 2; ks++) {
            uint32_t afh[4][4], afl[4][4], bfh[2][4], bfl[2][4];
#pragma unroll
            for (int mi = 0; mi < 4; mi++) {
                uint32_t ao = a_lane + (uint32_t)((mi * 16) * 80 + ks * 32);
                ldmx4(afh[mi], Ah + ao);
                ldmx4(afl[mi], Al + ao);
            }
#pragma unroll
            for (int j = 0; j < 2; j++) {
                uint32_t bo = b_lane + (uint32_t)((warp_col + j * 16) * 80 + ks * 32);
                ldmx4(bfh[j], Bh + bo);
                ldmx4(bfl[j], Bl + bo);
            }
#pragma unroll
            for (int mi = 0; mi < 4; mi++) {
#pragma unroll
                for (int ni = 0; ni < 4; ni++) {
                    const uint32_t* bh = &bfh[ni >> 1][(ni & 1) * 2];
                    const uint32_t* bl = &bfl[ni >> 1][(ni & 1) * 2];
                    mma_bf16(acc[mi][ni], afh[mi], bh);
                    mma_bf16(acc[mi][ni], afh[mi], bl);
                    mma_bf16(acc[mi][ni], afl[mi], bh);
                }
            }
        }
#pragma unroll
        for (int q = 0; q < 4; q++) pf_cur[q] = pf_nxt[q];
    }

    // epilogue: fp32 partial -> g_part[kseg]
    float* dst = &g_part[kseg][0];
    const int g = lid >> 2, t = lid & 3;
#pragma unroll
    for (int mi = 0; mi < 4; mi++) {
#pragma unroll
        for (int ni = 0; ni < 4; ni++) {
            int row0 = brow + mi * 16 + g;
            int row1 = row0 + 8;
            int col  = bn0 + warp_col + ni * 8 + 2 * t;
            const float* a = acc[mi][ni];
            *(float2*)(dst + (size_t)row0 * RANK + col) = make_float2(a[0], a[1]);
            *(float2*)(dst + (size_t)row1 * RANK + col) = make_float2(a[2], a[3]);
        }
    }
}

// ---------------------------------------------------------------------------
// k_finish: t = (p0 + p1) * schi -> g_t hi/lo
// ---------------------------------------------------------------------------
__global__ __launch_bounds__(256)
void k_finish()
{
    size_t i = ((size_t)blockIdx.x * 256 + threadIdx.x) * 4;
    float4 p0 = *(const float4*)(&g_part[0][i]);
    float4 p1 = *(const float4*)(&g_part[1][i]);
    float4 sc = *(const float4*)(g_schi + i);
    float4 t;
    t.x = (p0.x + p1.x) * sc.x;
    t.y = (p0.y + p1.y) * sc.y;
    t.z = (p0.z + p1.z) * sc.z;
    t.w = (p0.w + p1.w) * sc.w;
    ushort4 h, l;
    split2(t.x, h.x, l.x);
    split2(t.y, h.y, l.y);
    split2(t.z, h.z, l.z);
    split2(t.w, h.w, l.w);
    *(ushort4*)(g_t_hi + i) = h;
    *(ushort4*)(g_t_lo + i) = l;
}

// ---------------------------------------------------------------------------
// Launch.
// ---------------------------------------------------------------------------
extern "C" void kernel_launch(void* const* d_in, const int* in_sizes, int n_in,
                              void* d_out, int out_size)
{
    const float* inputs  = (const float*)d_in[0];
    const float* context = (const float*)d_in[1];
    const float* U       = (const float*)d_in[2];
    const float* S       = (const float*)d_in[3];
    const float* V       = (const float*)d_in[4];
    const float* W       = (const float*)d_in[5];
    const float* Bvec    = (const float*)d_in[6];
    const float* bias    = (const float*)d_in[7];
    float* out = (float*)d_out;

    const int smem_chi = 4 * (128 + 64) * 160;      // 122880
    const int smem_g1  = 2 * 10240 + 4 * 20480;     // 102400 -> 2 CTAs/SM
    const int smem_g2  = 2 * (128 + 128) * 160;     // 81920  -> 2 CTAs/SM

    cudaFuncSetAttribute(mma_gemm<128, 64, 4, 2, 512, 0, 4, 1>,
                         cudaFuncAttributeMaxDynamicSharedMemorySize, smem_chi);
    cudaFuncSetAttribute(gemm1_fused,
                         cudaFuncAttributeMaxDynamicSharedMemorySize, smem_g1);
    cudaFuncSetAttribute(mma_gemm<128, 128, 2, 4, 256, 2, 2, 2>,
                         cudaFuncAttributeMaxDynamicSharedMemorySize, smem_g2);

    // launch 0: prep1 (ctx split + W transpose)
    prep1<<<2048 + 128, 256>>>(context, W);
    // launch 1: chi = S*sigmoid(context @ W^T + B)
    mma_gemm<128, 64, 4, 2, 512, 0, 4, 1><<<dim3(RANK / 64, B_SZ / 128), 256, smem_chi>>>(
        nullptr, S, Bvec);
    // launch 2: prep2 (V split + U transpose)
    prep2<<<1024 + 1024, 256>>>(V, U);
    // launch 3 (profiled): gemm1 v2 — 64x128 tiles, MI=4, K-split x2
    gemm1_fused<<<dim3(RANK / 128, B_SZ / 64, 2), 128, smem_g1>>>(inputs);
    // launch 4: finish (reduce partials, scale by schi, split to bf16)
    k_finish<<<(B_SZ * RANK) / 1024, 256>>>();
    // launch 5: out = relu(t @ V^T + 2*bias)
    mma_gemm<128, 128, 2, 4, 256, 2, 2, 2><<<dim3(UNITS / 128, B_SZ / 128), 256, smem_g2>>>(
        out, bias, nullptr);
}